// round 12
// baseline (speedup 1.0000x reference)
#include <cuda_runtime.h>
#include <cuda_fp16.h>
#include <math.h>
#include <stdint.h>

// Problem constants (fixed by the dataset)
#define TT 5
#define FIN 10
#define HID 16
#define MAXN 100000
#define MAXE 3200000
#define XSTRIDE 64        // xT row stride in halves -> 128B aligned rows
#define XREAL  50
#define XREAL2 25         // half2 elements per xT row
#define F8STRIDE 128      // fp8 feature row stride in BYTES (80 data + pad)
#define FSTRIDE 80        // P row stride in halves (fp16)
#define K8 16.0f          // fp8 storage scale (keeps pre-scaled values normal)

// ---------------- device scratch (static: no allocation allowed) ----------------
__device__ int    g_cnt[MAXN];         // zero at load; re-zeroed each call
__device__ int    g_deg[MAXN];
__device__ int    g_row[MAXN];
__device__ int    g_cursor[MAXN];
__device__ int    g_total;
__device__ float  g_dis[MAXN];
__device__ __align__(16) int           g_csrc[MAXE];   // src index only (weights folded away)
__device__ __align__(16) __half        g_xT[(size_t)MAXN * XSTRIDE];      // dis[s]*x[s]
__device__ __align__(16) unsigned char g_h1[(size_t)MAXN * F8STRIDE];     // e4m3
__device__ __align__(16) unsigned char g_feats[(size_t)MAXN * F8STRIDE];  // e4m3
__device__ __align__(16) __half        g_P[(size_t)MAXN * FSTRIDE];
__device__ float  g_Mz[256], g_Mr[256], g_Mh[256];
__device__ float  g_Bz[16],  g_Br[16],  g_Bh[16];

__device__ __forceinline__ __half2 bits_h2u(unsigned b) {
    return *reinterpret_cast<__half2*>(&b);
}
__device__ __forceinline__ float fast_tanh(float x) {
    float r;
    asm("tanh.approx.f32 %0, %1;" : "=f"(r) : "f"(x));
    return r;
}
__device__ __forceinline__ float fast_sig(float x) {
    return fmaf(0.5f, fast_tanh(0.5f * x), 0.5f);
}
// packed fp32x2 helpers (Blackwell FFMA2 — PTX-only)
__device__ __forceinline__ unsigned long long pack2(float lo, float hi) {
    unsigned long long r;
    asm("mov.b64 %0, {%1, %2};" : "=l"(r) : "f"(lo), "f"(hi));
    return r;
}
__device__ __forceinline__ void unpack2(float& lo, float& hi, unsigned long long v) {
    asm("mov.b64 {%0, %1}, %2;" : "=f"(lo), "=f"(hi) : "l"(v));
}
__device__ __forceinline__ unsigned long long fma2(unsigned long long a,
                                                   unsigned long long b,
                                                   unsigned long long c) {
    unsigned long long d;
    asm("fma.rn.f32x2 %0, %1, %2, %3;" : "=l"(d) : "l"(a), "l"(b), "l"(c));
    return d;
}
// fp8 e4m3 pack/unpack
__device__ __forceinline__ unsigned pack_e4m3x4(float a, float b, float c, float d) {
    unsigned short lo, hi;
    asm("cvt.rn.satfinite.e4m3x2.f32 %0, %1, %2;" : "=h"(lo) : "f"(b), "f"(a));
    asm("cvt.rn.satfinite.e4m3x2.f32 %0, %1, %2;" : "=h"(hi) : "f"(d), "f"(c));
    return (unsigned)lo | ((unsigned)hi << 16);
}
__device__ __forceinline__ void unpack_e4m3x4(unsigned q, __half2& p01, __half2& p23) {
    unsigned a, b;
    asm("{\n\t"
        ".reg .b16 lo, hi;\n\t"
        "mov.b32 {lo, hi}, %2;\n\t"
        "cvt.rn.f16x2.e4m3x2 %0, lo;\n\t"
        "cvt.rn.f16x2.e4m3x2 %1, hi;\n\t"
        "}" : "=r"(a), "=r"(b) : "r"(q));
    p01 = bits_h2u(a);
    p23 = bits_h2u(b);
}

// ---------------- stage 1: degree count (x4 vectorized) --------------------------
__global__ void kcount(const int* __restrict__ dst, int* cnt, int e) {
    int i = blockIdx.x * blockDim.x + threadIdx.x;
    if (i == 0) g_total = 0;
    int j = i * 4;
    if (j + 4 <= e) {
        int4 d4 = __ldg((const int4*)(dst + j));
        atomicAdd(&cnt[d4.x], 1);
        atomicAdd(&cnt[d4.y], 1);
        atomicAdd(&cnt[d4.z], 1);
        atomicAdd(&cnt[d4.w], 1);
    } else {
        for (; j < e; j++) atomicAdd(&cnt[__ldg(dst + j)], 1);
    }
}

// per-block scan + single atomic -> contiguous (unordered) slices per node
__global__ __launch_bounds__(256) void koffsets(int* cnt, int n) {
    __shared__ int sh[256];
    __shared__ int sbase;
    int tid = threadIdx.x;
    int i = blockIdx.x * 256 + tid;
    int deg = (i < n) ? cnt[i] : 0;
    sh[tid] = deg;
    __syncthreads();
    for (int off = 1; off < 256; off <<= 1) {
        int t = (tid >= off) ? sh[tid - off] : 0;
        __syncthreads();
        sh[tid] += t;
        __syncthreads();
    }
    if (tid == 255) sbase = atomicAdd(&g_total, sh[255]);
    __syncthreads();
    int start = sbase + sh[tid] - deg;
    if (i < n) {
        g_row[i]    = start;
        g_cursor[i] = start;
        g_deg[i]    = deg;
        cnt[i]      = 0;                 // restore for next replay
        g_dis[i]    = rsqrtf((float)deg + 1.0f);
    }
}

// ---------------- stage 3: fused edge fill (x8) + x transpose (x2, fp16) ---------
__global__ void kfill2(const int* __restrict__ src, const int* __restrict__ dst,
                       int* cursor, int* csrc,
                       const float* __restrict__ x, __half* __restrict__ xT,
                       const float* __restrict__ dis, int n, int e) {
    int i = blockIdx.x * blockDim.x + threadIdx.x;
    int j = i * 8;
    if (j + 8 <= e) {
        int4 s0 = __ldg((const int4*)(src + j));
        int4 s1 = __ldg((const int4*)(src + j + 4));
        int4 d0 = __ldg((const int4*)(dst + j));
        int4 d1 = __ldg((const int4*)(dst + j + 4));
        csrc[atomicAdd(&cursor[d0.x], 1)] = s0.x;
        csrc[atomicAdd(&cursor[d0.y], 1)] = s0.y;
        csrc[atomicAdd(&cursor[d0.z], 1)] = s0.z;
        csrc[atomicAdd(&cursor[d0.w], 1)] = s0.w;
        csrc[atomicAdd(&cursor[d1.x], 1)] = s1.x;
        csrc[atomicAdd(&cursor[d1.y], 1)] = s1.y;
        csrc[atomicAdd(&cursor[d1.z], 1)] = s1.z;
        csrc[atomicAdd(&cursor[d1.w], 1)] = s1.w;
    } else {
        for (; j < e; j++)
            csrc[atomicAdd(&cursor[__ldg(dst + j)], 1)] = __ldg(src + j);
    }
    // transpose: 2 halves per thread (one half2 write)
    if (i < n * XREAL2) {
        int node = i / XREAL2;
        int c2 = i - node * XREAL2;
        int c = 2 * c2;            // even column in [0,50)
        int t = c / FIN;
        int f = c - t * FIN;       // even, f+1 < FIN
        float2 v = __ldg((const float2*)(x + ((size_t)t * n + node) * FIN + f));
        float dd = dis[node];
        __half2 h = __floats2half2_rn(dd * v.x, dd * v.y);
        ((unsigned*)xT)[(size_t)node * (XSTRIDE / 2) + c2] =
            *reinterpret_cast<unsigned*>(&h);
    }
}

// ---------------- stage 4: fp16 gather-sum -> fp8 transformed output -------------
__global__ __launch_bounds__(256, 8) void kprop_x(const __half* __restrict__ in,
                                                  unsigned char* __restrict__ out,
                                                  const int* __restrict__ rowp,
                                                  const int* __restrict__ degv,
                                                  const int* __restrict__ csrc,
                                                  const float* __restrict__ dis,
                                                  const float* __restrict__ Wm,
                                                  const float* __restrict__ bm, int n) {
    __shared__ float sAgg[8][52];
    __shared__ float sW[FIN * 16];
    __shared__ float sB[16];
    for (int i = threadIdx.x; i < FIN * 16; i += blockDim.x) sW[i] = Wm[i];
    if (threadIdx.x < 16) sB[threadIdx.x] = bm[threadIdx.x];
    __syncthreads();

    int wwid = threadIdx.x >> 5;
    int node = (blockIdx.x << 3) + wwid;
    if (node >= n) return;
    int lane = threadIdx.x & 31;
    int ll = (lane < 13) ? lane : 12;
    bool act = lane < 13;

    __half2 zero2 = __float2half2_rn(0.f);
    __half2 a0x = zero2, a0y = zero2, a1x = zero2, a1y = zero2;
    __half2 a2x = zero2, a2y = zero2, a3x = zero2, a3y = zero2;

    int j = rowp[node];
    int end = j + degv[node];

    while ((j & 3) && j < end) {
        int s = __ldg(csrc + j);
        uint2 q = __ldg((const uint2*)(in + (size_t)s * XSTRIDE) + ll);
        a0x = __hadd2(a0x, bits_h2u(q.x));
        a0y = __hadd2(a0y, bits_h2u(q.y));
        j++;
    }
    for (; j + 4 <= end; j += 4) {
        int4 e4 = __ldg((const int4*)(csrc + j));
        uint2 q0 = __ldg((const uint2*)(in + (size_t)e4.x * XSTRIDE) + ll);
        uint2 q1 = __ldg((const uint2*)(in + (size_t)e4.y * XSTRIDE) + ll);
        uint2 q2 = __ldg((const uint2*)(in + (size_t)e4.z * XSTRIDE) + ll);
        uint2 q3 = __ldg((const uint2*)(in + (size_t)e4.w * XSTRIDE) + ll);
        a0x = __hadd2(a0x, bits_h2u(q0.x)); a0y = __hadd2(a0y, bits_h2u(q0.y));
        a1x = __hadd2(a1x, bits_h2u(q1.x)); a1y = __hadd2(a1y, bits_h2u(q1.y));
        a2x = __hadd2(a2x, bits_h2u(q2.x)); a2y = __hadd2(a2y, bits_h2u(q2.y));
        a3x = __hadd2(a3x, bits_h2u(q3.x)); a3y = __hadd2(a3y, bits_h2u(q3.y));
    }
    for (; j < end; j++) {
        int s = __ldg(csrc + j);
        uint2 q = __ldg((const uint2*)(in + (size_t)s * XSTRIDE) + ll);
        a0x = __hadd2(a0x, bits_h2u(q.x));
        a0y = __hadd2(a0y, bits_h2u(q.y));
    }

    float dd = __ldg(dis + node);
    uint2 sq = __ldg((const uint2*)(in + (size_t)node * XSTRIDE) + ll);
    float2 s01 = __half22float2(bits_h2u(sq.x));
    float2 s23 = __half22float2(bits_h2u(sq.y));
    float2 c0, c1, c2, c3;
    c0 = __half22float2(a0x); c1 = __half22float2(a1x);
    c2 = __half22float2(a2x); c3 = __half22float2(a3x);
    float f0 = dd * ((c0.x + c1.x) + (c2.x + c3.x) + s01.x);
    float f1 = dd * ((c0.y + c1.y) + (c2.y + c3.y) + s01.y);
    c0 = __half22float2(a0y); c1 = __half22float2(a1y);
    c2 = __half22float2(a2y); c3 = __half22float2(a3y);
    float f2 = dd * ((c0.x + c1.x) + (c2.x + c3.x) + s23.x);
    float f3 = dd * ((c0.y + c1.y) + (c2.y + c3.y) + s23.y);

    if (act) {
        float4 fv = make_float4(f0, f1, f2, f3);
        *(float4*)&sAgg[wwid][lane * 4] = fv;
    }
    __syncwarp();
    if (lane < 20) {
        float ks = K8 * dd;
        int c = lane * 4;
        int t = c >> 4;
        int h = c & 15;
        float o0 = sB[h], o1 = sB[h + 1], o2 = sB[h + 2], o3 = sB[h + 3];
#pragma unroll
        for (int f = 0; f < FIN; f++) {
            float a = sAgg[wwid][t * FIN + f];
            o0 = fmaf(a, sW[f * 16 + h],     o0);
            o1 = fmaf(a, sW[f * 16 + h + 1], o1);
            o2 = fmaf(a, sW[f * 16 + h + 2], o2);
            o3 = fmaf(a, sW[f * 16 + h + 3], o3);
        }
        unsigned pk = pack_e4m3x4(ks * fmaxf(o0, 0.f), ks * fmaxf(o1, 0.f),
                                  ks * fmaxf(o2, 0.f), ks * fmaxf(o3, 0.f));
        ((unsigned*)(out + (size_t)node * F8STRIDE))[lane] = pk;
    }
}

// ---------------- stages 5/6: fp8 gather-sum --------------------------------------
template <int MODE>
__global__ __launch_bounds__(256, 8) void kprop8(const unsigned char* __restrict__ in,
                                                 void* __restrict__ outv,
                                                 const int* __restrict__ rowp,
                                                 const int* __restrict__ degv,
                                                 const int* __restrict__ csrc,
                                                 const float* __restrict__ dis,
                                                 const float* __restrict__ Wm,
                                                 const float* __restrict__ bm, int n) {
    __shared__ float sAgg[MODE ? 8 : 1][MODE ? 80 : 4];
    __shared__ float sW[MODE ? HID * 16 : 1];
    __shared__ float sB[MODE ? 16 : 1];
    if (MODE) {
        for (int i = threadIdx.x; i < HID * 16; i += blockDim.x) sW[i] = Wm[i];
        if (threadIdx.x < 16) sB[threadIdx.x] = bm[threadIdx.x];
        __syncthreads();
    }
    int wwid = threadIdx.x >> 5;
    int node = (blockIdx.x << 3) + wwid;
    if (node >= n) return;
    int lane = threadIdx.x & 31;
    int ll = (lane < 20) ? lane : 19;
    bool act = lane < 20;

    __half2 zero2 = __float2half2_rn(0.f);
    __half2 a0x = zero2, a0y = zero2, a1x = zero2, a1y = zero2;
    __half2 a2x = zero2, a2y = zero2, a3x = zero2, a3y = zero2;

    int j = rowp[node];
    int end = j + degv[node];

    while ((j & 3) && j < end) {
        int s = __ldg(csrc + j);
        unsigned q = __ldg((const unsigned*)(in + (size_t)s * F8STRIDE) + ll);
        __half2 pa, pb;
        unpack_e4m3x4(q, pa, pb);
        a0x = __hadd2(a0x, pa);
        a0y = __hadd2(a0y, pb);
        j++;
    }
    for (; j + 4 <= end; j += 4) {
        int4 e4 = __ldg((const int4*)(csrc + j));
        unsigned q0 = __ldg((const unsigned*)(in + (size_t)e4.x * F8STRIDE) + ll);
        unsigned q1 = __ldg((const unsigned*)(in + (size_t)e4.y * F8STRIDE) + ll);
        unsigned q2 = __ldg((const unsigned*)(in + (size_t)e4.z * F8STRIDE) + ll);
        unsigned q3 = __ldg((const unsigned*)(in + (size_t)e4.w * F8STRIDE) + ll);
        __half2 pa, pb;
        unpack_e4m3x4(q0, pa, pb);
        a0x = __hadd2(a0x, pa); a0y = __hadd2(a0y, pb);
        unpack_e4m3x4(q1, pa, pb);
        a1x = __hadd2(a1x, pa); a1y = __hadd2(a1y, pb);
        unpack_e4m3x4(q2, pa, pb);
        a2x = __hadd2(a2x, pa); a2y = __hadd2(a2y, pb);
        unpack_e4m3x4(q3, pa, pb);
        a3x = __hadd2(a3x, pa); a3y = __hadd2(a3y, pb);
    }
    for (; j < end; j++) {
        int s = __ldg(csrc + j);
        unsigned q = __ldg((const unsigned*)(in + (size_t)s * F8STRIDE) + ll);
        __half2 pa, pb;
        unpack_e4m3x4(q, pa, pb);
        a0x = __hadd2(a0x, pa);
        a0y = __hadd2(a0y, pb);
    }

    float dd = __ldg(dis + node);
    float sc = dd * (1.0f / K8);
    unsigned sq = __ldg((const unsigned*)(in + (size_t)node * F8STRIDE) + ll);
    __half2 sa, sb;
    unpack_e4m3x4(sq, sa, sb);
    float2 s01 = __half22float2(sa);
    float2 s23 = __half22float2(sb);
    float2 c0, c1, c2, c3;
    c0 = __half22float2(a0x); c1 = __half22float2(a1x);
    c2 = __half22float2(a2x); c3 = __half22float2(a3x);
    float f0 = sc * ((c0.x + c1.x) + (c2.x + c3.x) + s01.x);
    float f1 = sc * ((c0.y + c1.y) + (c2.y + c3.y) + s01.y);
    c0 = __half22float2(a0y); c1 = __half22float2(a1y);
    c2 = __half22float2(a2y); c3 = __half22float2(a3y);
    float f2 = sc * ((c0.x + c1.x) + (c2.x + c3.x) + s23.x);
    float f3 = sc * ((c0.y + c1.y) + (c2.y + c3.y) + s23.y);

    if (!MODE) {
        if (act) {
            __half2 o01 = __floats2half2_rn(f0, f1);
            __half2 o23 = __floats2half2_rn(f2, f3);
            uint2 pk;
            pk.x = *reinterpret_cast<unsigned*>(&o01);
            pk.y = *reinterpret_cast<unsigned*>(&o23);
            *((uint2*)((__half*)outv + (size_t)node * FSTRIDE) + lane) = pk;
        }
        return;
    }

    if (act) {
        float4 fv = make_float4(f0, f1, f2, f3);
        *(float4*)&sAgg[wwid][lane * 4] = fv;
    }
    __syncwarp();
    if (lane < 20) {
        float ks = K8 * dd;
        int c = lane * 4;
        int t = c >> 4;
        int h = c & 15;
        float o0 = sB[h], o1 = sB[h + 1], o2 = sB[h + 2], o3 = sB[h + 3];
#pragma unroll
        for (int f = 0; f < HID; f++) {
            float a = sAgg[wwid][t * HID + f];
            o0 = fmaf(a, sW[f * 16 + h],     o0);
            o1 = fmaf(a, sW[f * 16 + h + 1], o1);
            o2 = fmaf(a, sW[f * 16 + h + 2], o2);
            o3 = fmaf(a, sW[f * 16 + h + 3], o3);
        }
        unsigned pk = pack_e4m3x4(ks * fmaxf(o0, 0.f), ks * fmaxf(o1, 0.f),
                                  ks * fmaxf(o2, 0.f), ks * fmaxf(o3, 0.f));
        ((unsigned*)((unsigned char*)outv + (size_t)node * F8STRIDE))[lane] = pk;
    }
}

// ---------------- fold gate matmuls: M* = W* @ L*[0:16], B* = b*@L*[0:16] + l* ----
__global__ void kprepG(const float* Wz, const float* bz, const float* Wr, const float* br,
                       const float* Wh, const float* bh,
                       const float* Lz, const float* lz, const float* Lr, const float* lr,
                       const float* Lh, const float* lh) {
    int tid = threadIdx.x;  // 256
    int k = tid >> 4, h = tid & 15;
    float mz = 0.f, mr = 0.f, mh = 0.f;
#pragma unroll
    for (int j = 0; j < 16; j++) {
        mz = fmaf(Wz[k * 16 + j], Lz[j * 16 + h], mz);
        mr = fmaf(Wr[k * 16 + j], Lr[j * 16 + h], mr);
        mh = fmaf(Wh[k * 16 + j], Lh[j * 16 + h], mh);
    }
    g_Mz[tid] = mz; g_Mr[tid] = mr; g_Mh[tid] = mh;
    if (tid < 16) {
        float az = lz[tid], ar = lr[tid], ah = lh[tid];
#pragma unroll
        for (int j = 0; j < 16; j++) {
            az = fmaf(bz[j], Lz[j * 16 + tid], az);
            ar = fmaf(br[j], Lr[j * 16 + tid], ar);
            ah = fmaf(bh[j], Lh[j * 16 + tid], ah);
        }
        g_Bz[tid] = az; g_Br[tid] = ar; g_Bh[tid] = ah;
    }
}

// ---------------- GRU (FFMA2, half2-staged P) + attention + FC + log_softmax ----
#define GRU_NPB 96
__global__ __launch_bounds__(GRU_NPB) void kgru(const __half* __restrict__ P,
                                                const float* __restrict__ Lz,
                                                const float* __restrict__ Lr,
                                                const float* __restrict__ Lh,
                                                const float* __restrict__ att,
                                                const float* __restrict__ fcW,
                                                const float* __restrict__ fcb,
                                                float* __restrict__ out, int n) {
    __shared__ unsigned long long sM2z[128], sM2r[128], sM2h[128];
    __shared__ unsigned long long sL2z[128], sL2r[128], sL2h[128];
    __shared__ unsigned long long sB2z[8], sB2r[8], sB2h[8];
    __shared__ unsigned sPh[GRU_NPB * 41];   // 40 half2 per node + 1 pad (bank-safe)
    __shared__ float sfcW[32], sfcb[2], sprob[TT];

    int tid = threadIdx.x;
    for (int i = tid; i < 128; i += GRU_NPB) {
        int k = i >> 3, j = i & 7;
        int gi = k * 16 + 2 * j;
        sM2z[i] = pack2(g_Mz[gi], g_Mz[gi + 1]);
        sM2r[i] = pack2(g_Mr[gi], g_Mr[gi + 1]);
        sM2h[i] = pack2(g_Mh[gi], g_Mh[gi + 1]);
        sL2z[i] = pack2(Lz[256 + gi], Lz[256 + gi + 1]);
        sL2r[i] = pack2(Lr[256 + gi], Lr[256 + gi + 1]);
        sL2h[i] = pack2(Lh[256 + gi], Lh[256 + gi + 1]);
    }
    if (tid < 8) {
        sB2z[tid] = pack2(g_Bz[2 * tid], g_Bz[2 * tid + 1]);
        sB2r[tid] = pack2(g_Br[2 * tid], g_Br[2 * tid + 1]);
        sB2h[tid] = pack2(g_Bh[2 * tid], g_Bh[2 * tid + 1]);
    }
    if (tid < 32) sfcW[tid] = fcW[tid];
    if (tid < 2)  sfcb[tid] = fcb[tid];
    if (tid == 0) {
        float m = att[0];
        for (int t = 1; t < TT; t++) m = fmaxf(m, att[t]);
        float ex[TT]; float s = 0.f;
        for (int t = 0; t < TT; t++) { ex[t] = expf(att[t] - m); s += ex[t]; }
        for (int t = 0; t < TT; t++) sprob[t] = ex[t] / s;
    }
    int base = blockIdx.x * GRU_NPB;
    for (int i = tid; i < GRU_NPB * (FSTRIDE / 2); i += GRU_NPB) {
        int nd = i / (FSTRIDE / 2), c2 = i - nd * (FSTRIDE / 2);
        int g = base + nd;
        unsigned u = 0;
        if (g < n) u = __ldg((const unsigned*)(P + (size_t)g * FSTRIDE) + c2);
        sPh[nd * 41 + c2] = u;
    }
    __syncthreads();

    int node = base + tid;
    if (node >= n) return;
    const unsigned* myPh = &sPh[tid * 41];

    float H[16], Hacc[16];
#pragma unroll
    for (int h = 0; h < 16; h++) { H[h] = 0.f; Hacc[h] = 0.f; }

#pragma unroll 1
    for (int t = 0; t < TT; t++) {
        unsigned long long pk2[16], hk2[16];
#pragma unroll
        for (int k2 = 0; k2 < 8; k2++) {
            float2 pf = __half22float2(bits_h2u(myPh[t * 8 + k2]));
            pk2[2 * k2]     = pack2(pf.x, pf.x);
            pk2[2 * k2 + 1] = pack2(pf.y, pf.y);
        }
#pragma unroll
        for (int k = 0; k < 16; k++) hk2[k] = pack2(H[k], H[k]);

        unsigned long long acc[8];
        float a[16];
        // Z gate
#pragma unroll
        for (int j = 0; j < 8; j++) acc[j] = sB2z[j];
#pragma unroll
        for (int k = 0; k < 16; k++) {
#pragma unroll
            for (int j = 0; j < 8; j++) {
                acc[j] = fma2(pk2[k], sM2z[k * 8 + j], acc[j]);
                acc[j] = fma2(hk2[k], sL2z[k * 8 + j], acc[j]);
            }
        }
        float Zg[16];
#pragma unroll
        for (int j = 0; j < 8; j++) unpack2(a[2 * j], a[2 * j + 1], acc[j]);
#pragma unroll
        for (int h = 0; h < 16; h++) Zg[h] = fast_sig(a[h]);

        // R gate
#pragma unroll
        for (int j = 0; j < 8; j++) acc[j] = sB2r[j];
#pragma unroll
        for (int k = 0; k < 16; k++) {
#pragma unroll
            for (int j = 0; j < 8; j++) {
                acc[j] = fma2(pk2[k], sM2r[k * 8 + j], acc[j]);
                acc[j] = fma2(hk2[k], sL2r[k * 8 + j], acc[j]);
            }
        }
        float Rg[16];
#pragma unroll
        for (int j = 0; j < 8; j++) unpack2(a[2 * j], a[2 * j + 1], acc[j]);
#pragma unroll
        for (int h = 0; h < 16; h++) Rg[h] = fast_sig(a[h]);

        // candidate gate: uses H*Rg
#pragma unroll
        for (int k = 0; k < 16; k++) {
            float hr = H[k] * Rg[k];
            hk2[k] = pack2(hr, hr);
        }
#pragma unroll
        for (int j = 0; j < 8; j++) acc[j] = sB2h[j];
#pragma unroll
        for (int k = 0; k < 16; k++) {
#pragma unroll
            for (int j = 0; j < 8; j++) {
                acc[j] = fma2(pk2[k], sM2h[k * 8 + j], acc[j]);
                acc[j] = fma2(hk2[k], sL2h[k * 8 + j], acc[j]);
            }
        }
#pragma unroll
        for (int j = 0; j < 8; j++) unpack2(a[2 * j], a[2 * j + 1], acc[j]);
#pragma unroll
        for (int h = 0; h < 16; h++) {
            float ht = fast_tanh(a[h]);
            H[h] = Zg[h] * H[h] + (1.f - Zg[h]) * ht;
            Hacc[h] = fmaf(sprob[t], H[h], Hacc[h]);
        }
    }

    float l0 = sfcb[0], l1 = sfcb[1];
#pragma unroll
    for (int h = 0; h < 16; h++) {
        l0 = fmaf(Hacc[h], sfcW[h * 2 + 0], l0);
        l1 = fmaf(Hacc[h], sfcW[h * 2 + 1], l1);
    }
    float m = fmaxf(l0, l1);
    float lse = m + logf(expf(l0 - m) + expf(l1 - m));
    out[(size_t)node * 2 + 0] = l0 - lse;
    out[(size_t)node * 2 + 1] = l1 - lse;
}

// ---------------- launch ----------------
extern "C" void kernel_launch(void* const* d_in, const int* in_sizes, int n_in,
                              void* d_out, int out_size) {
    const float* x   = (const float*)d_in[0];
    const int*   src = (const int*)d_in[1];
    const int*   dst = (const int*)d_in[2];
    const float* W1  = (const float*)d_in[3];
    const float* b1  = (const float*)d_in[4];
    const float* W2  = (const float*)d_in[5];
    const float* b2  = (const float*)d_in[6];
    const float* Wz  = (const float*)d_in[7];
    const float* bz  = (const float*)d_in[8];
    const float* Wr  = (const float*)d_in[9];
    const float* br  = (const float*)d_in[10];
    const float* Wh  = (const float*)d_in[11];
    const float* bh  = (const float*)d_in[12];
    const float* Lz  = (const float*)d_in[13];
    const float* lz  = (const float*)d_in[14];
    const float* Lr  = (const float*)d_in[15];
    const float* lr  = (const float*)d_in[16];
    const float* Lh  = (const float*)d_in[17];
    const float* lh  = (const float*)d_in[18];
    const float* att = (const float*)d_in[19];
    const float* fcW = (const float*)d_in[20];
    const float* fcb = (const float*)d_in[21];

    int n = in_sizes[0] / (TT * FIN);
    int e = in_sizes[1];

    void* p;
    cudaGetSymbolAddress(&p, g_cnt);     int*           cnt    = (int*)p;
    cudaGetSymbolAddress(&p, g_deg);     int*           degv   = (int*)p;
    cudaGetSymbolAddress(&p, g_row);     int*           rowp   = (int*)p;
    cudaGetSymbolAddress(&p, g_cursor);  int*           cursor = (int*)p;
    cudaGetSymbolAddress(&p, g_dis);     float*         dis    = (float*)p;
    cudaGetSymbolAddress(&p, g_csrc);    int*           csrc   = (int*)p;
    cudaGetSymbolAddress(&p, g_xT);      __half*        xT     = (__half*)p;
    cudaGetSymbolAddress(&p, g_h1);      unsigned char* h1     = (unsigned char*)p;
    cudaGetSymbolAddress(&p, g_feats);   unsigned char* feats  = (unsigned char*)p;
    cudaGetSymbolAddress(&p, g_P);       __half*        P      = (__half*)p;

    int nb256_n = (n + 255) / 256;
    int e4 = (e + 3) / 4;
    int e8 = (e + 7) / 8;
    int fill_threads = (e8 > n * XREAL2) ? e8 : n * XREAL2;
    int prop_blocks = (n + 7) / 8;

    // 0: fold GRU gate weights (independent; keeps kfill2 in profiled slot 3)
    kprepG<<<1, 256>>>(Wz, bz, Wr, br, Wh, bh, Lz, lz, Lr, lr, Lh, lh);
    // 1: degree count (x4 vectorized)
    kcount<<<(e4 + 255) / 256, 256>>>(dst, cnt, e);
    // 2: offsets + dis
    koffsets<<<nb256_n, 256>>>(cnt, n);
    // 3: fused edge fill (x8) + x transpose (x2)    <-- profiled slot
    kfill2<<<(fill_threads + 255) / 256, 256>>>(src, dst, cursor, csrc, x, xT, dis, n, e);
    // 4: h1(fp8) = K8*dis*relu((S x) @ W1 + b1)
    kprop_x<<<prop_blocks, 256>>>(xT, h1, rowp, degv, csrc, dis, W1, b1, n);
    // 5: feats(fp8) = K8*dis*relu((S h1) @ W2 + b2)
    kprop8<1><<<prop_blocks, 256>>>(h1, feats, rowp, degv, csrc, dis, W2, b2, n);
    // 6: P(fp16) = S feats
    kprop8<0><<<prop_blocks, 256>>>(feats, P, rowp, degv, csrc, dis, W2, b2, n);
    // 7: GRU (FFMA2, half2-staged P) + attention + FC + log_softmax
    kgru<<<(n + GRU_NPB - 1) / GRU_NPB, GRU_NPB>>>(P, Lz, Lr, Lh, att, fcW, fcb,
                                                   (float*)d_out, n);
}

// round 13
// speedup vs baseline: 1.0354x; 1.0354x over previous
#include <cuda_runtime.h>
#include <cuda_fp16.h>
#include <math.h>
#include <stdint.h>

// Problem constants (fixed by the dataset)
#define TT 5
#define FIN 10
#define HID 16
#define MAXN 100000
#define MAXE 3200000
#define CAP 96            // fixed CSR slice capacity per node (P(deg>96) ~ 1e-13)
#define XSTRIDE 64        // xT row stride in halves -> 128B aligned rows
#define XREAL  50
#define XREAL2 25         // half2 elements per xT row
#define F8STRIDE 128      // fp8 feature row stride in BYTES (80 data + pad)
#define FSTRIDE 80        // P row stride in halves (fp16)
#define K8 16.0f          // fp8 storage scale

// ---------------- device scratch (static: no allocation allowed) ----------------
__device__ int    g_cursor[MAXN];
__device__ float  g_dis[MAXN];
__device__ __align__(16) int           g_csrc[(size_t)MAXN * CAP];  // fixed slices
__device__ __align__(16) __half        g_xT[(size_t)MAXN * XSTRIDE];      // dis[s]*x[s]
__device__ __align__(16) unsigned char g_h1[(size_t)MAXN * F8STRIDE];     // e4m3
__device__ __align__(16) unsigned char g_feats[(size_t)MAXN * F8STRIDE];  // e4m3
__device__ __align__(16) __half        g_P[(size_t)MAXN * FSTRIDE];
__device__ float  g_Mz[256], g_Mr[256], g_Mh[256];
__device__ float  g_Bz[16],  g_Br[16],  g_Bh[16];

__device__ __forceinline__ __half2 bits_h2u(unsigned b) {
    return *reinterpret_cast<__half2*>(&b);
}
__device__ __forceinline__ float fast_tanh(float x) {
    float r;
    asm("tanh.approx.f32 %0, %1;" : "=f"(r) : "f"(x));
    return r;
}
__device__ __forceinline__ float fast_sig(float x) {
    return fmaf(0.5f, fast_tanh(0.5f * x), 0.5f);
}
// packed fp32x2 helpers (Blackwell FFMA2 — PTX-only)
__device__ __forceinline__ unsigned long long pack2(float lo, float hi) {
    unsigned long long r;
    asm("mov.b64 %0, {%1, %2};" : "=l"(r) : "f"(lo), "f"(hi));
    return r;
}
__device__ __forceinline__ void unpack2(float& lo, float& hi, unsigned long long v) {
    asm("mov.b64 {%0, %1}, %2;" : "=f"(lo), "=f"(hi) : "l"(v));
}
__device__ __forceinline__ unsigned long long fma2(unsigned long long a,
                                                   unsigned long long b,
                                                   unsigned long long c) {
    unsigned long long d;
    asm("fma.rn.f32x2 %0, %1, %2, %3;" : "=l"(d) : "l"(a), "l"(b), "l"(c));
    return d;
}
// fp8 e4m3 pack/unpack
__device__ __forceinline__ unsigned pack_e4m3x4(float a, float b, float c, float d) {
    unsigned short lo, hi;
    asm("cvt.rn.satfinite.e4m3x2.f32 %0, %1, %2;" : "=h"(lo) : "f"(b), "f"(a));
    asm("cvt.rn.satfinite.e4m3x2.f32 %0, %1, %2;" : "=h"(hi) : "f"(d), "f"(c));
    return (unsigned)lo | ((unsigned)hi << 16);
}
__device__ __forceinline__ void unpack_e4m3x4(unsigned q, __half2& p01, __half2& p23) {
    unsigned a, b;
    asm("{\n\t"
        ".reg .b16 lo, hi;\n\t"
        "mov.b32 {lo, hi}, %2;\n\t"
        "cvt.rn.f16x2.e4m3x2 %0, lo;\n\t"
        "cvt.rn.f16x2.e4m3x2 %1, hi;\n\t"
        "}" : "=r"(a), "=r"(b) : "r"(q));
    p01 = bits_h2u(a);
    p23 = bits_h2u(b);
}

// ---------------- stage 1: cursor init (replaces degree count + scan) ------------
__global__ void kinit(int* cursor, int n) {
    int i = blockIdx.x * blockDim.x + threadIdx.x;
    if (i < n) cursor[i] = i * CAP;
}

// ---------------- stage 2: edge fill into fixed slices (single atomic pass) ------
__global__ void kfill(const int* __restrict__ src, const int* __restrict__ dst,
                      int* cursor, int* csrc, int e) {
    int i = blockIdx.x * blockDim.x + threadIdx.x;
    int j = i * 8;
    if (j + 8 <= e) {
        int4 s0 = __ldg((const int4*)(src + j));
        int4 s1 = __ldg((const int4*)(src + j + 4));
        int4 d0 = __ldg((const int4*)(dst + j));
        int4 d1 = __ldg((const int4*)(dst + j + 4));
        int p;
        p = atomicAdd(&cursor[d0.x], 1); if (p < d0.x * CAP + CAP) csrc[p] = s0.x;
        p = atomicAdd(&cursor[d0.y], 1); if (p < d0.y * CAP + CAP) csrc[p] = s0.y;
        p = atomicAdd(&cursor[d0.z], 1); if (p < d0.z * CAP + CAP) csrc[p] = s0.z;
        p = atomicAdd(&cursor[d0.w], 1); if (p < d0.w * CAP + CAP) csrc[p] = s0.w;
        p = atomicAdd(&cursor[d1.x], 1); if (p < d1.x * CAP + CAP) csrc[p] = s1.x;
        p = atomicAdd(&cursor[d1.y], 1); if (p < d1.y * CAP + CAP) csrc[p] = s1.y;
        p = atomicAdd(&cursor[d1.z], 1); if (p < d1.z * CAP + CAP) csrc[p] = s1.z;
        p = atomicAdd(&cursor[d1.w], 1); if (p < d1.w * CAP + CAP) csrc[p] = s1.w;
    } else {
        for (; j < e; j++) {
            int d = __ldg(dst + j);
            int p = atomicAdd(&cursor[d], 1);
            if (p < d * CAP + CAP) csrc[p] = __ldg(src + j);
        }
    }
}

// ---------------- stage 3: x transpose pre-scaled by dis (+ write dis) -----------
__global__ void ktransd(const float* __restrict__ x, __half* __restrict__ xT,
                        const int* __restrict__ cursor, float* __restrict__ dis,
                        int n) {
    int i = blockIdx.x * blockDim.x + threadIdx.x;
    if (i >= n * XREAL2) return;
    int node = i / XREAL2;
    int c2 = i - node * XREAL2;
    int deg = __ldg(cursor + node) - node * CAP;   // actual degree
    float dd = rsqrtf((float)deg + 1.0f);
    if (c2 == 0) dis[node] = dd;
    int c = 2 * c2;
    int t = c / FIN;
    int f = c - t * FIN;
    float2 v = __ldg((const float2*)(x + ((size_t)t * n + node) * FIN + f));
    __half2 h = __floats2half2_rn(dd * v.x, dd * v.y);
    ((unsigned*)xT)[(size_t)node * (XSTRIDE / 2) + c2] =
        *reinterpret_cast<unsigned*>(&h);
}

// ---------------- stage 4: fp16 gather-sum -> fp8 transformed output -------------
__global__ __launch_bounds__(256, 8) void kprop_x(const __half* __restrict__ in,
                                                  unsigned char* __restrict__ out,
                                                  const int* __restrict__ cursor,
                                                  const int* __restrict__ csrc,
                                                  const float* __restrict__ dis,
                                                  const float* __restrict__ Wm,
                                                  const float* __restrict__ bm, int n) {
    __shared__ float sAgg[8][52];
    __shared__ float sW[FIN * 16];
    __shared__ float sB[16];
    for (int i = threadIdx.x; i < FIN * 16; i += blockDim.x) sW[i] = Wm[i];
    if (threadIdx.x < 16) sB[threadIdx.x] = bm[threadIdx.x];
    __syncthreads();

    int wwid = threadIdx.x >> 5;
    int node = (blockIdx.x << 3) + wwid;
    if (node >= n) return;
    int lane = threadIdx.x & 31;
    int ll = (lane < 13) ? lane : 12;
    bool act = lane < 13;

    __half2 zero2 = __float2half2_rn(0.f);
    __half2 a0x = zero2, a0y = zero2, a1x = zero2, a1y = zero2;
    __half2 a2x = zero2, a2y = zero2, a3x = zero2, a3y = zero2;

    int j = node * CAP;                           // 384B-aligned slice start
    int end = __ldg(cursor + node);
    if (end > j + CAP) end = j + CAP;

    for (; j + 4 <= end; j += 4) {
        int4 e4 = __ldg((const int4*)(csrc + j));
        uint2 q0 = __ldg((const uint2*)(in + (size_t)e4.x * XSTRIDE) + ll);
        uint2 q1 = __ldg((const uint2*)(in + (size_t)e4.y * XSTRIDE) + ll);
        uint2 q2 = __ldg((const uint2*)(in + (size_t)e4.z * XSTRIDE) + ll);
        uint2 q3 = __ldg((const uint2*)(in + (size_t)e4.w * XSTRIDE) + ll);
        a0x = __hadd2(a0x, bits_h2u(q0.x)); a0y = __hadd2(a0y, bits_h2u(q0.y));
        a1x = __hadd2(a1x, bits_h2u(q1.x)); a1y = __hadd2(a1y, bits_h2u(q1.y));
        a2x = __hadd2(a2x, bits_h2u(q2.x)); a2y = __hadd2(a2y, bits_h2u(q2.y));
        a3x = __hadd2(a3x, bits_h2u(q3.x)); a3y = __hadd2(a3y, bits_h2u(q3.y));
    }
    for (; j < end; j++) {
        int s = __ldg(csrc + j);
        uint2 q = __ldg((const uint2*)(in + (size_t)s * XSTRIDE) + ll);
        a0x = __hadd2(a0x, bits_h2u(q.x));
        a0y = __hadd2(a0y, bits_h2u(q.y));
    }

    float dd = __ldg(dis + node);
    uint2 sq = __ldg((const uint2*)(in + (size_t)node * XSTRIDE) + ll);
    float2 s01 = __half22float2(bits_h2u(sq.x));
    float2 s23 = __half22float2(bits_h2u(sq.y));
    float2 c0, c1, c2, c3;
    c0 = __half22float2(a0x); c1 = __half22float2(a1x);
    c2 = __half22float2(a2x); c3 = __half22float2(a3x);
    float f0 = dd * ((c0.x + c1.x) + (c2.x + c3.x) + s01.x);
    float f1 = dd * ((c0.y + c1.y) + (c2.y + c3.y) + s01.y);
    c0 = __half22float2(a0y); c1 = __half22float2(a1y);
    c2 = __half22float2(a2y); c3 = __half22float2(a3y);
    float f2 = dd * ((c0.x + c1.x) + (c2.x + c3.x) + s23.x);
    float f3 = dd * ((c0.y + c1.y) + (c2.y + c3.y) + s23.y);

    if (act) {
        float4 fv = make_float4(f0, f1, f2, f3);
        *(float4*)&sAgg[wwid][lane * 4] = fv;
    }
    __syncwarp();
    if (lane < 20) {
        float ks = K8 * dd;
        int c = lane * 4;
        int t = c >> 4;
        int h = c & 15;
        float o0 = sB[h], o1 = sB[h + 1], o2 = sB[h + 2], o3 = sB[h + 3];
#pragma unroll
        for (int f = 0; f < FIN; f++) {
            float a = sAgg[wwid][t * FIN + f];
            o0 = fmaf(a, sW[f * 16 + h],     o0);
            o1 = fmaf(a, sW[f * 16 + h + 1], o1);
            o2 = fmaf(a, sW[f * 16 + h + 2], o2);
            o3 = fmaf(a, sW[f * 16 + h + 3], o3);
        }
        unsigned pk = pack_e4m3x4(ks * fmaxf(o0, 0.f), ks * fmaxf(o1, 0.f),
                                  ks * fmaxf(o2, 0.f), ks * fmaxf(o3, 0.f));
        ((unsigned*)(out + (size_t)node * F8STRIDE))[lane] = pk;
    }
}

// ---------------- stages 5/6: fp8 gather-sum --------------------------------------
template <int MODE>
__global__ __launch_bounds__(256, 8) void kprop8(const unsigned char* __restrict__ in,
                                                 void* __restrict__ outv,
                                                 const int* __restrict__ cursor,
                                                 const int* __restrict__ csrc,
                                                 const float* __restrict__ dis,
                                                 const float* __restrict__ Wm,
                                                 const float* __restrict__ bm, int n) {
    __shared__ float sAgg[MODE ? 8 : 1][MODE ? 80 : 4];
    __shared__ float sW[MODE ? HID * 16 : 1];
    __shared__ float sB[MODE ? 16 : 1];
    if (MODE) {
        for (int i = threadIdx.x; i < HID * 16; i += blockDim.x) sW[i] = Wm[i];
        if (threadIdx.x < 16) sB[threadIdx.x] = bm[threadIdx.x];
        __syncthreads();
    }
    int wwid = threadIdx.x >> 5;
    int node = (blockIdx.x << 3) + wwid;
    if (node >= n) return;
    int lane = threadIdx.x & 31;
    int ll = (lane < 20) ? lane : 19;
    bool act = lane < 20;

    __half2 zero2 = __float2half2_rn(0.f);
    __half2 a0x = zero2, a0y = zero2, a1x = zero2, a1y = zero2;
    __half2 a2x = zero2, a2y = zero2, a3x = zero2, a3y = zero2;

    int j = node * CAP;
    int end = __ldg(cursor + node);
    if (end > j + CAP) end = j + CAP;

    for (; j + 4 <= end; j += 4) {
        int4 e4 = __ldg((const int4*)(csrc + j));
        unsigned q0 = __ldg((const unsigned*)(in + (size_t)e4.x * F8STRIDE) + ll);
        unsigned q1 = __ldg((const unsigned*)(in + (size_t)e4.y * F8STRIDE) + ll);
        unsigned q2 = __ldg((const unsigned*)(in + (size_t)e4.z * F8STRIDE) + ll);
        unsigned q3 = __ldg((const unsigned*)(in + (size_t)e4.w * F8STRIDE) + ll);
        __half2 pa, pb;
        unpack_e4m3x4(q0, pa, pb);
        a0x = __hadd2(a0x, pa); a0y = __hadd2(a0y, pb);
        unpack_e4m3x4(q1, pa, pb);
        a1x = __hadd2(a1x, pa); a1y = __hadd2(a1y, pb);
        unpack_e4m3x4(q2, pa, pb);
        a2x = __hadd2(a2x, pa); a2y = __hadd2(a2y, pb);
        unpack_e4m3x4(q3, pa, pb);
        a3x = __hadd2(a3x, pa); a3y = __hadd2(a3y, pb);
    }
    for (; j < end; j++) {
        int s = __ldg(csrc + j);
        unsigned q = __ldg((const unsigned*)(in + (size_t)s * F8STRIDE) + ll);
        __half2 pa, pb;
        unpack_e4m3x4(q, pa, pb);
        a0x = __hadd2(a0x, pa);
        a0y = __hadd2(a0y, pb);
    }

    float dd = __ldg(dis + node);
    float sc = dd * (1.0f / K8);
    unsigned sq = __ldg((const unsigned*)(in + (size_t)node * F8STRIDE) + ll);
    __half2 sa, sb;
    unpack_e4m3x4(sq, sa, sb);
    float2 s01 = __half22float2(sa);
    float2 s23 = __half22float2(sb);
    float2 c0, c1, c2, c3;
    c0 = __half22float2(a0x); c1 = __half22float2(a1x);
    c2 = __half22float2(a2x); c3 = __half22float2(a3x);
    float f0 = sc * ((c0.x + c1.x) + (c2.x + c3.x) + s01.x);
    float f1 = sc * ((c0.y + c1.y) + (c2.y + c3.y) + s01.y);
    c0 = __half22float2(a0y); c1 = __half22float2(a1y);
    c2 = __half22float2(a2y); c3 = __half22float2(a3y);
    float f2 = sc * ((c0.x + c1.x) + (c2.x + c3.x) + s23.x);
    float f3 = sc * ((c0.y + c1.y) + (c2.y + c3.y) + s23.y);

    if (!MODE) {
        if (act) {
            __half2 o01 = __floats2half2_rn(f0, f1);
            __half2 o23 = __floats2half2_rn(f2, f3);
            uint2 pk;
            pk.x = *reinterpret_cast<unsigned*>(&o01);
            pk.y = *reinterpret_cast<unsigned*>(&o23);
            *((uint2*)((__half*)outv + (size_t)node * FSTRIDE) + lane) = pk;
        }
        return;
    }

    if (act) {
        float4 fv = make_float4(f0, f1, f2, f3);
        *(float4*)&sAgg[wwid][lane * 4] = fv;
    }
    __syncwarp();
    if (lane < 20) {
        float ks = K8 * dd;
        int c = lane * 4;
        int t = c >> 4;
        int h = c & 15;
        float o0 = sB[h], o1 = sB[h + 1], o2 = sB[h + 2], o3 = sB[h + 3];
#pragma unroll
        for (int f = 0; f < HID; f++) {
            float a = sAgg[wwid][t * HID + f];
            o0 = fmaf(a, sW[f * 16 + h],     o0);
            o1 = fmaf(a, sW[f * 16 + h + 1], o1);
            o2 = fmaf(a, sW[f * 16 + h + 2], o2);
            o3 = fmaf(a, sW[f * 16 + h + 3], o3);
        }
        unsigned pk = pack_e4m3x4(ks * fmaxf(o0, 0.f), ks * fmaxf(o1, 0.f),
                                  ks * fmaxf(o2, 0.f), ks * fmaxf(o3, 0.f));
        ((unsigned*)((unsigned char*)outv + (size_t)node * F8STRIDE))[lane] = pk;
    }
}

// ---------------- fold gate matmuls: M* = W* @ L*[0:16], B* = b*@L*[0:16] + l* ----
__global__ void kprepG(const float* Wz, const float* bz, const float* Wr, const float* br,
                       const float* Wh, const float* bh,
                       const float* Lz, const float* lz, const float* Lr, const float* lr,
                       const float* Lh, const float* lh) {
    int tid = threadIdx.x;  // 256
    int k = tid >> 4, h = tid & 15;
    float mz = 0.f, mr = 0.f, mh = 0.f;
#pragma unroll
    for (int j = 0; j < 16; j++) {
        mz = fmaf(Wz[k * 16 + j], Lz[j * 16 + h], mz);
        mr = fmaf(Wr[k * 16 + j], Lr[j * 16 + h], mr);
        mh = fmaf(Wh[k * 16 + j], Lh[j * 16 + h], mh);
    }
    g_Mz[tid] = mz; g_Mr[tid] = mr; g_Mh[tid] = mh;
    if (tid < 16) {
        float az = lz[tid], ar = lr[tid], ah = lh[tid];
#pragma unroll
        for (int j = 0; j < 16; j++) {
            az = fmaf(bz[j], Lz[j * 16 + tid], az);
            ar = fmaf(br[j], Lr[j * 16 + tid], ar);
            ah = fmaf(bh[j], Lh[j * 16 + tid], ah);
        }
        g_Bz[tid] = az; g_Br[tid] = ar; g_Bh[tid] = ah;
    }
}

// ---------------- GRU (FFMA2, half2-staged P) + attention + FC + log_softmax ----
#define GRU_NPB 96
__global__ __launch_bounds__(GRU_NPB) void kgru(const __half* __restrict__ P,
                                                const float* __restrict__ Lz,
                                                const float* __restrict__ Lr,
                                                const float* __restrict__ Lh,
                                                const float* __restrict__ att,
                                                const float* __restrict__ fcW,
                                                const float* __restrict__ fcb,
                                                float* __restrict__ out, int n) {
    __shared__ unsigned long long sM2z[128], sM2r[128], sM2h[128];
    __shared__ unsigned long long sL2z[128], sL2r[128], sL2h[128];
    __shared__ unsigned long long sB2z[8], sB2r[8], sB2h[8];
    __shared__ unsigned sPh[GRU_NPB * 41];   // 40 half2 per node + 1 pad
    __shared__ float sfcW[32], sfcb[2], sprob[TT];

    int tid = threadIdx.x;
    for (int i = tid; i < 128; i += GRU_NPB) {
        int k = i >> 3, j = i & 7;
        int gi = k * 16 + 2 * j;
        sM2z[i] = pack2(g_Mz[gi], g_Mz[gi + 1]);
        sM2r[i] = pack2(g_Mr[gi], g_Mr[gi + 1]);
        sM2h[i] = pack2(g_Mh[gi], g_Mh[gi + 1]);
        sL2z[i] = pack2(Lz[256 + gi], Lz[256 + gi + 1]);
        sL2r[i] = pack2(Lr[256 + gi], Lr[256 + gi + 1]);
        sL2h[i] = pack2(Lh[256 + gi], Lh[256 + gi + 1]);
    }
    if (tid < 8) {
        sB2z[tid] = pack2(g_Bz[2 * tid], g_Bz[2 * tid + 1]);
        sB2r[tid] = pack2(g_Br[2 * tid], g_Br[2 * tid + 1]);
        sB2h[tid] = pack2(g_Bh[2 * tid], g_Bh[2 * tid + 1]);
    }
    if (tid < 32) sfcW[tid] = fcW[tid];
    if (tid < 2)  sfcb[tid] = fcb[tid];
    if (tid == 0) {
        float m = att[0];
        for (int t = 1; t < TT; t++) m = fmaxf(m, att[t]);
        float ex[TT]; float s = 0.f;
        for (int t = 0; t < TT; t++) { ex[t] = expf(att[t] - m); s += ex[t]; }
        for (int t = 0; t < TT; t++) sprob[t] = ex[t] / s;
    }
    int base = blockIdx.x * GRU_NPB;
    for (int i = tid; i < GRU_NPB * (FSTRIDE / 2); i += GRU_NPB) {
        int nd = i / (FSTRIDE / 2), c2 = i - nd * (FSTRIDE / 2);
        int g = base + nd;
        unsigned u = 0;
        if (g < n) u = __ldg((const unsigned*)(P + (size_t)g * FSTRIDE) + c2);
        sPh[nd * 41 + c2] = u;
    }
    __syncthreads();

    int node = base + tid;
    if (node >= n) return;
    const unsigned* myPh = &sPh[tid * 41];

    float H[16], Hacc[16];
#pragma unroll
    for (int h = 0; h < 16; h++) { H[h] = 0.f; Hacc[h] = 0.f; }

#pragma unroll 1
    for (int t = 0; t < TT; t++) {
        unsigned long long pk2[16], hk2[16];
#pragma unroll
        for (int k2 = 0; k2 < 8; k2++) {
            float2 pf = __half22float2(bits_h2u(myPh[t * 8 + k2]));
            pk2[2 * k2]     = pack2(pf.x, pf.x);
            pk2[2 * k2 + 1] = pack2(pf.y, pf.y);
        }
#pragma unroll
        for (int k = 0; k < 16; k++) hk2[k] = pack2(H[k], H[k]);

        unsigned long long acc[8];
        float a[16];
        // Z gate
#pragma unroll
        for (int j = 0; j < 8; j++) acc[j] = sB2z[j];
#pragma unroll
        for (int k = 0; k < 16; k++) {
#pragma unroll
            for (int j = 0; j < 8; j++) {
                acc[j] = fma2(pk2[k], sM2z[k * 8 + j], acc[j]);
                acc[j] = fma2(hk2[k], sL2z[k * 8 + j], acc[j]);
            }
        }
        float Zg[16];
#pragma unroll
        for (int j = 0; j < 8; j++) unpack2(a[2 * j], a[2 * j + 1], acc[j]);
#pragma unroll
        for (int h = 0; h < 16; h++) Zg[h] = fast_sig(a[h]);

        // R gate
#pragma unroll
        for (int j = 0; j < 8; j++) acc[j] = sB2r[j];
#pragma unroll
        for (int k = 0; k < 16; k++) {
#pragma unroll
            for (int j = 0; j < 8; j++) {
                acc[j] = fma2(pk2[k], sM2r[k * 8 + j], acc[j]);
                acc[j] = fma2(hk2[k], sL2r[k * 8 + j], acc[j]);
            }
        }
        float Rg[16];
#pragma unroll
        for (int j = 0; j < 8; j++) unpack2(a[2 * j], a[2 * j + 1], acc[j]);
#pragma unroll
        for (int h = 0; h < 16; h++) Rg[h] = fast_sig(a[h]);

        // candidate gate
#pragma unroll
        for (int k = 0; k < 16; k++) {
            float hr = H[k] * Rg[k];
            hk2[k] = pack2(hr, hr);
        }
#pragma unroll
        for (int j = 0; j < 8; j++) acc[j] = sB2h[j];
#pragma unroll
        for (int k = 0; k < 16; k++) {
#pragma unroll
            for (int j = 0; j < 8; j++) {
                acc[j] = fma2(pk2[k], sM2h[k * 8 + j], acc[j]);
                acc[j] = fma2(hk2[k], sL2h[k * 8 + j], acc[j]);
            }
        }
#pragma unroll
        for (int j = 0; j < 8; j++) unpack2(a[2 * j], a[2 * j + 1], acc[j]);
#pragma unroll
        for (int h = 0; h < 16; h++) {
            float ht = fast_tanh(a[h]);
            H[h] = Zg[h] * H[h] + (1.f - Zg[h]) * ht;
            Hacc[h] = fmaf(sprob[t], H[h], Hacc[h]);
        }
    }

    float l0 = sfcb[0], l1 = sfcb[1];
#pragma unroll
    for (int h = 0; h < 16; h++) {
        l0 = fmaf(Hacc[h], sfcW[h * 2 + 0], l0);
        l1 = fmaf(Hacc[h], sfcW[h * 2 + 1], l1);
    }
    float m = fmaxf(l0, l1);
    float lse = m + logf(expf(l0 - m) + expf(l1 - m));
    out[(size_t)node * 2 + 0] = l0 - lse;
    out[(size_t)node * 2 + 1] = l1 - lse;
}

// ---------------- launch ----------------
extern "C" void kernel_launch(void* const* d_in, const int* in_sizes, int n_in,
                              void* d_out, int out_size) {
    const float* x   = (const float*)d_in[0];
    const int*   src = (const int*)d_in[1];
    const int*   dst = (const int*)d_in[2];
    const float* W1  = (const float*)d_in[3];
    const float* b1  = (const float*)d_in[4];
    const float* W2  = (const float*)d_in[5];
    const float* b2  = (const float*)d_in[6];
    const float* Wz  = (const float*)d_in[7];
    const float* bz  = (const float*)d_in[8];
    const float* Wr  = (const float*)d_in[9];
    const float* br  = (const float*)d_in[10];
    const float* Wh  = (const float*)d_in[11];
    const float* bh  = (const float*)d_in[12];
    const float* Lz  = (const float*)d_in[13];
    const float* lz  = (const float*)d_in[14];
    const float* Lr  = (const float*)d_in[15];
    const float* lr  = (const float*)d_in[16];
    const float* Lh  = (const float*)d_in[17];
    const float* lh  = (const float*)d_in[18];
    const float* att = (const float*)d_in[19];
    const float* fcW = (const float*)d_in[20];
    const float* fcb = (const float*)d_in[21];

    int n = in_sizes[0] / (TT * FIN);
    int e = in_sizes[1];

    void* p;
    cudaGetSymbolAddress(&p, g_cursor);  int*           cursor = (int*)p;
    cudaGetSymbolAddress(&p, g_dis);     float*         dis    = (float*)p;
    cudaGetSymbolAddress(&p, g_csrc);    int*           csrc   = (int*)p;
    cudaGetSymbolAddress(&p, g_xT);      __half*        xT     = (__half*)p;
    cudaGetSymbolAddress(&p, g_h1);      unsigned char* h1     = (unsigned char*)p;
    cudaGetSymbolAddress(&p, g_feats);   unsigned char* feats  = (unsigned char*)p;
    cudaGetSymbolAddress(&p, g_P);       __half*        P      = (__half*)p;

    int nb256_n = (n + 255) / 256;
    int e8 = (e + 7) / 8;
    int prop_blocks = (n + 7) / 8;

    // 0: fold GRU gate weights
    kprepG<<<1, 256>>>(Wz, bz, Wr, br, Wh, bh, Lz, lz, Lr, lr, Lh, lh);
    // 1: cursor init (fixed-capacity slices; replaces count+scan)
    kinit<<<nb256_n, 256>>>(cursor, n);
    // 2: single-pass edge fill
    kfill<<<(e8 + 255) / 256, 256>>>(src, dst, cursor, csrc, e);
    // 3: x transpose pre-scaled by dis (computed from cursor)   <-- profiled slot
    ktransd<<<(n * XREAL2 + 255) / 256, 256>>>(x, xT, cursor, dis, n);
    // 4: h1(fp8) = K8*dis*relu((S x) @ W1 + b1)
    kprop_x<<<prop_blocks, 256>>>(xT, h1, cursor, csrc, dis, W1, b1, n);
    // 5: feats(fp8) = K8*dis*relu((S h1) @ W2 + b2)
    kprop8<1><<<prop_blocks, 256>>>(h1, feats, cursor, csrc, dis, W2, b2, n);
    // 6: P(fp16) = S feats
    kprop8<0><<<prop_blocks, 256>>>(feats, P, cursor, csrc, dis, W2, b2, n);
    // 7: GRU (FFMA2) + attention + FC + log_softmax
    kgru<<<(n + GRU_NPB - 1) / GRU_NPB, GRU_NPB>>>(P, Lz, Lr, Lh, att, fcW, fcb,
                                                   (float*)d_out, n);
}

// round 14
// speedup vs baseline: 1.0499x; 1.0140x over previous
#include <cuda_runtime.h>
#include <cuda_fp16.h>
#include <math.h>
#include <stdint.h>

// Problem constants (fixed by the dataset)
#define TT 5
#define FIN 10
#define HID 16
#define MAXN 100000
#define MAXE 3200000
#define CAP 96            // fixed CSR slice capacity per node (P(deg>96) ~ 1e-13)
#define XSTRIDE 64        // xT row stride in halves -> 128B aligned rows
#define XREAL  50
#define XREAL2 25         // half2 elements per xT row
#define F8STRIDE 128      // fp8 feature row stride in BYTES (80 data + pad)
#define FSTRIDE 80        // P row stride in halves (fp16)
#define K8 16.0f          // fp8 storage scale

// ---------------- device scratch (static: no allocation allowed) ----------------
__device__ int    g_cursor[MAXN];
__device__ float  g_dis[MAXN];
__device__ __align__(16) int           g_csrc[(size_t)MAXN * CAP];  // fixed slices
__device__ __align__(16) __half        g_xT[(size_t)MAXN * XSTRIDE];      // dis[s]*x[s]
__device__ __align__(16) unsigned char g_h1[(size_t)MAXN * F8STRIDE];     // e4m3
__device__ __align__(16) unsigned char g_feats[(size_t)MAXN * F8STRIDE];  // e4m3
__device__ __align__(16) __half        g_P[(size_t)MAXN * FSTRIDE];
__device__ float  g_Mz[256], g_Mr[256], g_Mh[256];
__device__ float  g_Bz[16],  g_Br[16],  g_Bh[16];

__device__ __forceinline__ __half2 bits_h2u(unsigned b) {
    return *reinterpret_cast<__half2*>(&b);
}
__device__ __forceinline__ float fast_tanh(float x) {
    float r;
    asm("tanh.approx.f32 %0, %1;" : "=f"(r) : "f"(x));
    return r;
}
__device__ __forceinline__ float fast_sig(float x) {
    return fmaf(0.5f, fast_tanh(0.5f * x), 0.5f);
}
// packed fp32x2 helpers (Blackwell FFMA2 — PTX-only)
__device__ __forceinline__ unsigned long long pack2(float lo, float hi) {
    unsigned long long r;
    asm("mov.b64 %0, {%1, %2};" : "=l"(r) : "f"(lo), "f"(hi));
    return r;
}
__device__ __forceinline__ void unpack2(float& lo, float& hi, unsigned long long v) {
    asm("mov.b64 {%0, %1}, %2;" : "=f"(lo), "=f"(hi) : "l"(v));
}
__device__ __forceinline__ unsigned long long fma2(unsigned long long a,
                                                   unsigned long long b,
                                                   unsigned long long c) {
    unsigned long long d;
    asm("fma.rn.f32x2 %0, %1, %2, %3;" : "=l"(d) : "l"(a), "l"(b), "l"(c));
    return d;
}
// fp8 e4m3 pack/unpack
__device__ __forceinline__ unsigned pack_e4m3x4(float a, float b, float c, float d) {
    unsigned short lo, hi;
    asm("cvt.rn.satfinite.e4m3x2.f32 %0, %1, %2;" : "=h"(lo) : "f"(b), "f"(a));
    asm("cvt.rn.satfinite.e4m3x2.f32 %0, %1, %2;" : "=h"(hi) : "f"(d), "f"(c));
    return (unsigned)lo | ((unsigned)hi << 16);
}
__device__ __forceinline__ void unpack_e4m3x4(unsigned q, __half2& p01, __half2& p23) {
    unsigned a, b;
    asm("{\n\t"
        ".reg .b16 lo, hi;\n\t"
        "mov.b32 {lo, hi}, %2;\n\t"
        "cvt.rn.f16x2.e4m3x2 %0, lo;\n\t"
        "cvt.rn.f16x2.e4m3x2 %1, hi;\n\t"
        "}" : "=r"(a), "=r"(b) : "r"(q));
    p01 = bits_h2u(a);
    p23 = bits_h2u(b);
}

// ---------------- stage 1: cursor init -------------------------------------------
__global__ void kinit(int* cursor, int n) {
    int i = blockIdx.x * blockDim.x + threadIdx.x;
    if (i < n) cursor[i] = i * CAP;
}

// ---------------- stage 2: edge fill into fixed slices (single atomic pass) ------
__global__ void kfill(const int* __restrict__ src, const int* __restrict__ dst,
                      int* cursor, int* csrc, int e) {
    int i = blockIdx.x * blockDim.x + threadIdx.x;
    int j = i * 8;
    if (j + 8 <= e) {
        int4 s0 = __ldg((const int4*)(src + j));
        int4 s1 = __ldg((const int4*)(src + j + 4));
        int4 d0 = __ldg((const int4*)(dst + j));
        int4 d1 = __ldg((const int4*)(dst + j + 4));
        int p;
        p = atomicAdd(&cursor[d0.x], 1); if (p < d0.x * CAP + CAP) csrc[p] = s0.x;
        p = atomicAdd(&cursor[d0.y], 1); if (p < d0.y * CAP + CAP) csrc[p] = s0.y;
        p = atomicAdd(&cursor[d0.z], 1); if (p < d0.z * CAP + CAP) csrc[p] = s0.z;
        p = atomicAdd(&cursor[d0.w], 1); if (p < d0.w * CAP + CAP) csrc[p] = s0.w;
        p = atomicAdd(&cursor[d1.x], 1); if (p < d1.x * CAP + CAP) csrc[p] = s1.x;
        p = atomicAdd(&cursor[d1.y], 1); if (p < d1.y * CAP + CAP) csrc[p] = s1.y;
        p = atomicAdd(&cursor[d1.z], 1); if (p < d1.z * CAP + CAP) csrc[p] = s1.z;
        p = atomicAdd(&cursor[d1.w], 1); if (p < d1.w * CAP + CAP) csrc[p] = s1.w;
    } else {
        for (; j < e; j++) {
            int d = __ldg(dst + j);
            int p = atomicAdd(&cursor[d], 1);
            if (p < d * CAP + CAP) csrc[p] = __ldg(src + j);
        }
    }
}

// ---------------- stage 3: x transpose pre-scaled by dis (+ write dis) -----------
__global__ void ktransd(const float* __restrict__ x, __half* __restrict__ xT,
                        const int* __restrict__ cursor, float* __restrict__ dis,
                        int n) {
    int i = blockIdx.x * blockDim.x + threadIdx.x;
    if (i >= n * XREAL2) return;
    int node = i / XREAL2;
    int c2 = i - node * XREAL2;
    int deg = __ldg(cursor + node) - node * CAP;
    float dd = rsqrtf((float)deg + 1.0f);
    if (c2 == 0) dis[node] = dd;
    int c = 2 * c2;
    int t = c / FIN;
    int f = c - t * FIN;
    float2 v = __ldg((const float2*)(x + ((size_t)t * n + node) * FIN + f));
    __half2 h = __floats2half2_rn(dd * v.x, dd * v.y);
    ((unsigned*)xT)[(size_t)node * (XSTRIDE / 2) + c2] =
        *reinterpret_cast<unsigned*>(&h);
}

// ---------------- stage 4: dual-row fp16 gather-sum -> fp8 transformed output ----
// Lanes 0-12 gather even edges' rows, lanes 16-28 gather odd edges' rows in the
// SAME LDG instruction (2 lines, 1 issue). Cross-group merge via shfl at the end.
__global__ __launch_bounds__(256, 8) void kprop_x(const __half* __restrict__ in,
                                                  unsigned char* __restrict__ out,
                                                  const int* __restrict__ cursor,
                                                  const int* __restrict__ csrc,
                                                  const float* __restrict__ dis,
                                                  const float* __restrict__ Wm,
                                                  const float* __restrict__ bm, int n) {
    __shared__ float sAgg[8][52];
    __shared__ float sW[FIN * 16];
    __shared__ float sB[16];
    for (int i = threadIdx.x; i < FIN * 16; i += blockDim.x) sW[i] = Wm[i];
    if (threadIdx.x < 16) sB[threadIdx.x] = bm[threadIdx.x];
    __syncthreads();

    int wwid = threadIdx.x >> 5;
    int node = (blockIdx.x << 3) + wwid;
    if (node >= n) return;
    int lane = threadIdx.x & 31;
    bool grp = lane >= 16;                 // group 1 handles odd edges
    int lh = lane & 15;
    int ll = (lh < 13) ? lh : 12;          // half2-pair index within row
    const unsigned FULL = 0xffffffffu;

    __half2 zero2 = __float2half2_rn(0.f);
    __half2 a0x = zero2, a0y = zero2, a1x = zero2, a1y = zero2;

    int j = node * CAP;                    // 384B-aligned slice start
    int end = __ldg(cursor + node);
    if (end > j + CAP) end = j + CAP;

    for (; j + 4 <= end; j += 4) {
        int4 e4 = __ldg((const int4*)(csrc + j));
        int sA = grp ? e4.y : e4.x;        // pair 0: edges j, j+1
        int sB2 = grp ? e4.w : e4.z;       // pair 1: edges j+2, j+3
        uint2 q0 = __ldg((const uint2*)(in + (size_t)sA * XSTRIDE) + ll);
        uint2 q1 = __ldg((const uint2*)(in + (size_t)sB2 * XSTRIDE) + ll);
        a0x = __hadd2(a0x, bits_h2u(q0.x));
        a0y = __hadd2(a0y, bits_h2u(q0.y));
        a1x = __hadd2(a1x, bits_h2u(q1.x));
        a1y = __hadd2(a1y, bits_h2u(q1.y));
    }
    // remainder: pairs of edges (dual), then possibly one single edge
    if (j + 2 <= end) {
        int sA = csrc[j + (grp ? 1 : 0)];
        uint2 q = __ldg((const uint2*)(in + (size_t)sA * XSTRIDE) + ll);
        a0x = __hadd2(a0x, bits_h2u(q.x));
        a0y = __hadd2(a0y, bits_h2u(q.y));
        j += 2;
    }
    if (j < end) {
        int s = csrc[j];
        uint2 q = __ldg((const uint2*)(in + (size_t)s * XSTRIDE) + ll);
        if (!grp) {                        // only group 0 accumulates the odd one
            a0x = __hadd2(a0x, bits_h2u(q.x));
            a0y = __hadd2(a0y, bits_h2u(q.y));
        }
    }

    // merge local chains to fp32
    float2 c0 = __half22float2(a0x);
    float2 c1 = __half22float2(a1x);
    float f0 = c0.x + c1.x;
    float f1 = c0.y + c1.y;
    c0 = __half22float2(a0y);
    c1 = __half22float2(a1y);
    float f2 = c0.x + c1.x;
    float f3 = c0.y + c1.y;
    // cross-group merge (lane l += lane l+16)
    f0 += __shfl_down_sync(FULL, f0, 16);
    f1 += __shfl_down_sync(FULL, f1, 16);
    f2 += __shfl_down_sync(FULL, f2, 16);
    f3 += __shfl_down_sync(FULL, f3, 16);

    // self row + scale (valid in lanes 0-12)
    float dd = __ldg(dis + node);
    uint2 sq = __ldg((const uint2*)(in + (size_t)node * XSTRIDE) + ll);
    float2 s01 = __half22float2(bits_h2u(sq.x));
    float2 s23 = __half22float2(bits_h2u(sq.y));
    f0 = dd * (f0 + s01.x);
    f1 = dd * (f1 + s01.y);
    f2 = dd * (f2 + s23.x);
    f3 = dd * (f3 + s23.y);

    if (lane < 13) {
        float4 fv = make_float4(f0, f1, f2, f3);
        *(float4*)&sAgg[wwid][lane * 4] = fv;
    }
    __syncwarp();
    if (lane < 20) {
        float ks = K8 * dd;
        int c = lane * 4;
        int t = c >> 4;
        int h = c & 15;
        float o0 = sB[h], o1 = sB[h + 1], o2 = sB[h + 2], o3 = sB[h + 3];
#pragma unroll
        for (int f = 0; f < FIN; f++) {
            float a = sAgg[wwid][t * FIN + f];
            o0 = fmaf(a, sW[f * 16 + h],     o0);
            o1 = fmaf(a, sW[f * 16 + h + 1], o1);
            o2 = fmaf(a, sW[f * 16 + h + 2], o2);
            o3 = fmaf(a, sW[f * 16 + h + 3], o3);
        }
        unsigned pk = pack_e4m3x4(ks * fmaxf(o0, 0.f), ks * fmaxf(o1, 0.f),
                                  ks * fmaxf(o2, 0.f), ks * fmaxf(o3, 0.f));
        ((unsigned*)(out + (size_t)node * F8STRIDE))[lane] = pk;
    }
}

// ---------------- stages 5/6: fp8 gather-sum (unchanged, at empirical floor) -----
template <int MODE>
__global__ __launch_bounds__(256, 8) void kprop8(const unsigned char* __restrict__ in,
                                                 void* __restrict__ outv,
                                                 const int* __restrict__ cursor,
                                                 const int* __restrict__ csrc,
                                                 const float* __restrict__ dis,
                                                 const float* __restrict__ Wm,
                                                 const float* __restrict__ bm, int n) {
    __shared__ float sAgg[MODE ? 8 : 1][MODE ? 80 : 4];
    __shared__ float sW[MODE ? HID * 16 : 1];
    __shared__ float sB[MODE ? 16 : 1];
    if (MODE) {
        for (int i = threadIdx.x; i < HID * 16; i += blockDim.x) sW[i] = Wm[i];
        if (threadIdx.x < 16) sB[threadIdx.x] = bm[threadIdx.x];
        __syncthreads();
    }
    int wwid = threadIdx.x >> 5;
    int node = (blockIdx.x << 3) + wwid;
    if (node >= n) return;
    int lane = threadIdx.x & 31;
    int ll = (lane < 20) ? lane : 19;
    bool act = lane < 20;

    __half2 zero2 = __float2half2_rn(0.f);
    __half2 a0x = zero2, a0y = zero2, a1x = zero2, a1y = zero2;
    __half2 a2x = zero2, a2y = zero2, a3x = zero2, a3y = zero2;

    int j = node * CAP;
    int end = __ldg(cursor + node);
    if (end > j + CAP) end = j + CAP;

    for (; j + 4 <= end; j += 4) {
        int4 e4 = __ldg((const int4*)(csrc + j));
        unsigned q0 = __ldg((const unsigned*)(in + (size_t)e4.x * F8STRIDE) + ll);
        unsigned q1 = __ldg((const unsigned*)(in + (size_t)e4.y * F8STRIDE) + ll);
        unsigned q2 = __ldg((const unsigned*)(in + (size_t)e4.z * F8STRIDE) + ll);
        unsigned q3 = __ldg((const unsigned*)(in + (size_t)e4.w * F8STRIDE) + ll);
        __half2 pa, pb;
        unpack_e4m3x4(q0, pa, pb);
        a0x = __hadd2(a0x, pa); a0y = __hadd2(a0y, pb);
        unpack_e4m3x4(q1, pa, pb);
        a1x = __hadd2(a1x, pa); a1y = __hadd2(a1y, pb);
        unpack_e4m3x4(q2, pa, pb);
        a2x = __hadd2(a2x, pa); a2y = __hadd2(a2y, pb);
        unpack_e4m3x4(q3, pa, pb);
        a3x = __hadd2(a3x, pa); a3y = __hadd2(a3y, pb);
    }
    for (; j < end; j++) {
        int s = __ldg(csrc + j);
        unsigned q = __ldg((const unsigned*)(in + (size_t)s * F8STRIDE) + ll);
        __half2 pa, pb;
        unpack_e4m3x4(q, pa, pb);
        a0x = __hadd2(a0x, pa);
        a0y = __hadd2(a0y, pb);
    }

    float dd = __ldg(dis + node);
    float sc = dd * (1.0f / K8);
    unsigned sq = __ldg((const unsigned*)(in + (size_t)node * F8STRIDE) + ll);
    __half2 sa, sb;
    unpack_e4m3x4(sq, sa, sb);
    float2 s01 = __half22float2(sa);
    float2 s23 = __half22float2(sb);
    float2 c0, c1, c2, c3;
    c0 = __half22float2(a0x); c1 = __half22float2(a1x);
    c2 = __half22float2(a2x); c3 = __half22float2(a3x);
    float f0 = sc * ((c0.x + c1.x) + (c2.x + c3.x) + s01.x);
    float f1 = sc * ((c0.y + c1.y) + (c2.y + c3.y) + s01.y);
    c0 = __half22float2(a0y); c1 = __half22float2(a1y);
    c2 = __half22float2(a2y); c3 = __half22float2(a3y);
    float f2 = sc * ((c0.x + c1.x) + (c2.x + c3.x) + s23.x);
    float f3 = sc * ((c0.y + c1.y) + (c2.y + c3.y) + s23.y);

    if (!MODE) {
        if (act) {
            __half2 o01 = __floats2half2_rn(f0, f1);
            __half2 o23 = __floats2half2_rn(f2, f3);
            uint2 pk;
            pk.x = *reinterpret_cast<unsigned*>(&o01);
            pk.y = *reinterpret_cast<unsigned*>(&o23);
            *((uint2*)((__half*)outv + (size_t)node * FSTRIDE) + lane) = pk;
        }
        return;
    }

    if (act) {
        float4 fv = make_float4(f0, f1, f2, f3);
        *(float4*)&sAgg[wwid][lane * 4] = fv;
    }
    __syncwarp();
    if (lane < 20) {
        float ks = K8 * dd;
        int c = lane * 4;
        int t = c >> 4;
        int h = c & 15;
        float o0 = sB[h], o1 = sB[h + 1], o2 = sB[h + 2], o3 = sB[h + 3];
#pragma unroll
        for (int f = 0; f < HID; f++) {
            float a = sAgg[wwid][t * HID + f];
            o0 = fmaf(a, sW[f * 16 + h],     o0);
            o1 = fmaf(a, sW[f * 16 + h + 1], o1);
            o2 = fmaf(a, sW[f * 16 + h + 2], o2);
            o3 = fmaf(a, sW[f * 16 + h + 3], o3);
        }
        unsigned pk = pack_e4m3x4(ks * fmaxf(o0, 0.f), ks * fmaxf(o1, 0.f),
                                  ks * fmaxf(o2, 0.f), ks * fmaxf(o3, 0.f));
        ((unsigned*)((unsigned char*)outv + (size_t)node * F8STRIDE))[lane] = pk;
    }
}

// ---------------- fold gate matmuls ----------------------------------------------
__global__ void kprepG(const float* Wz, const float* bz, const float* Wr, const float* br,
                       const float* Wh, const float* bh,
                       const float* Lz, const float* lz, const float* Lr, const float* lr,
                       const float* Lh, const float* lh) {
    int tid = threadIdx.x;  // 256
    int k = tid >> 4, h = tid & 15;
    float mz = 0.f, mr = 0.f, mh = 0.f;
#pragma unroll
    for (int j = 0; j < 16; j++) {
        mz = fmaf(Wz[k * 16 + j], Lz[j * 16 + h], mz);
        mr = fmaf(Wr[k * 16 + j], Lr[j * 16 + h], mr);
        mh = fmaf(Wh[k * 16 + j], Lh[j * 16 + h], mh);
    }
    g_Mz[tid] = mz; g_Mr[tid] = mr; g_Mh[tid] = mh;
    if (tid < 16) {
        float az = lz[tid], ar = lr[tid], ah = lh[tid];
#pragma unroll
        for (int j = 0; j < 16; j++) {
            az = fmaf(bz[j], Lz[j * 16 + tid], az);
            ar = fmaf(br[j], Lr[j * 16 + tid], ar);
            ah = fmaf(bh[j], Lh[j * 16 + tid], ah);
        }
        g_Bz[tid] = az; g_Br[tid] = ar; g_Bh[tid] = ah;
    }
}

// ---------------- GRU (FFMA2, half2-staged P) + attention + FC + log_softmax ----
#define GRU_NPB 96
__global__ __launch_bounds__(GRU_NPB) void kgru(const __half* __restrict__ P,
                                                const float* __restrict__ Lz,
                                                const float* __restrict__ Lr,
                                                const float* __restrict__ Lh,
                                                const float* __restrict__ att,
                                                const float* __restrict__ fcW,
                                                const float* __restrict__ fcb,
                                                float* __restrict__ out, int n) {
    __shared__ unsigned long long sM2z[128], sM2r[128], sM2h[128];
    __shared__ unsigned long long sL2z[128], sL2r[128], sL2h[128];
    __shared__ unsigned long long sB2z[8], sB2r[8], sB2h[8];
    __shared__ unsigned sPh[GRU_NPB * 41];
    __shared__ float sfcW[32], sfcb[2], sprob[TT];

    int tid = threadIdx.x;
    for (int i = tid; i < 128; i += GRU_NPB) {
        int k = i >> 3, j = i & 7;
        int gi = k * 16 + 2 * j;
        sM2z[i] = pack2(g_Mz[gi], g_Mz[gi + 1]);
        sM2r[i] = pack2(g_Mr[gi], g_Mr[gi + 1]);
        sM2h[i] = pack2(g_Mh[gi], g_Mh[gi + 1]);
        sL2z[i] = pack2(Lz[256 + gi], Lz[256 + gi + 1]);
        sL2r[i] = pack2(Lr[256 + gi], Lr[256 + gi + 1]);
        sL2h[i] = pack2(Lh[256 + gi], Lh[256 + gi + 1]);
    }
    if (tid < 8) {
        sB2z[tid] = pack2(g_Bz[2 * tid], g_Bz[2 * tid + 1]);
        sB2r[tid] = pack2(g_Br[2 * tid], g_Br[2 * tid + 1]);
        sB2h[tid] = pack2(g_Bh[2 * tid], g_Bh[2 * tid + 1]);
    }
    if (tid < 32) sfcW[tid] = fcW[tid];
    if (tid < 2)  sfcb[tid] = fcb[tid];
    if (tid == 0) {
        float m = att[0];
        for (int t = 1; t < TT; t++) m = fmaxf(m, att[t]);
        float ex[TT]; float s = 0.f;
        for (int t = 0; t < TT; t++) { ex[t] = expf(att[t] - m); s += ex[t]; }
        for (int t = 0; t < TT; t++) sprob[t] = ex[t] / s;
    }
    int base = blockIdx.x * GRU_NPB;
    for (int i = tid; i < GRU_NPB * (FSTRIDE / 2); i += GRU_NPB) {
        int nd = i / (FSTRIDE / 2), c2 = i - nd * (FSTRIDE / 2);
        int g = base + nd;
        unsigned u = 0;
        if (g < n) u = __ldg((const unsigned*)(P + (size_t)g * FSTRIDE) + c2);
        sPh[nd * 41 + c2] = u;
    }
    __syncthreads();

    int node = base + tid;
    if (node >= n) return;
    const unsigned* myPh = &sPh[tid * 41];

    float H[16], Hacc[16];
#pragma unroll
    for (int h = 0; h < 16; h++) { H[h] = 0.f; Hacc[h] = 0.f; }

#pragma unroll 1
    for (int t = 0; t < TT; t++) {
        unsigned long long pk2[16], hk2[16];
#pragma unroll
        for (int k2 = 0; k2 < 8; k2++) {
            float2 pf = __half22float2(bits_h2u(myPh[t * 8 + k2]));
            pk2[2 * k2]     = pack2(pf.x, pf.x);
            pk2[2 * k2 + 1] = pack2(pf.y, pf.y);
        }
#pragma unroll
        for (int k = 0; k < 16; k++) hk2[k] = pack2(H[k], H[k]);

        unsigned long long acc[8];
        float a[16];
#pragma unroll
        for (int j = 0; j < 8; j++) acc[j] = sB2z[j];
#pragma unroll
        for (int k = 0; k < 16; k++) {
#pragma unroll
            for (int j = 0; j < 8; j++) {
                acc[j] = fma2(pk2[k], sM2z[k * 8 + j], acc[j]);
                acc[j] = fma2(hk2[k], sL2z[k * 8 + j], acc[j]);
            }
        }
        float Zg[16];
#pragma unroll
        for (int j = 0; j < 8; j++) unpack2(a[2 * j], a[2 * j + 1], acc[j]);
#pragma unroll
        for (int h = 0; h < 16; h++) Zg[h] = fast_sig(a[h]);

#pragma unroll
        for (int j = 0; j < 8; j++) acc[j] = sB2r[j];
#pragma unroll
        for (int k = 0; k < 16; k++) {
#pragma unroll
            for (int j = 0; j < 8; j++) {
                acc[j] = fma2(pk2[k], sM2r[k * 8 + j], acc[j]);
                acc[j] = fma2(hk2[k], sL2r[k * 8 + j], acc[j]);
            }
        }
        float Rg[16];
#pragma unroll
        for (int j = 0; j < 8; j++) unpack2(a[2 * j], a[2 * j + 1], acc[j]);
#pragma unroll
        for (int h = 0; h < 16; h++) Rg[h] = fast_sig(a[h]);

#pragma unroll
        for (int k = 0; k < 16; k++) {
            float hr = H[k] * Rg[k];
            hk2[k] = pack2(hr, hr);
        }
#pragma unroll
        for (int j = 0; j < 8; j++) acc[j] = sB2h[j];
#pragma unroll
        for (int k = 0; k < 16; k++) {
#pragma unroll
            for (int j = 0; j < 8; j++) {
                acc[j] = fma2(pk2[k], sM2h[k * 8 + j], acc[j]);
                acc[j] = fma2(hk2[k], sL2h[k * 8 + j], acc[j]);
            }
        }
#pragma unroll
        for (int j = 0; j < 8; j++) unpack2(a[2 * j], a[2 * j + 1], acc[j]);
#pragma unroll
        for (int h = 0; h < 16; h++) {
            float ht = fast_tanh(a[h]);
            H[h] = Zg[h] * H[h] + (1.f - Zg[h]) * ht;
            Hacc[h] = fmaf(sprob[t], H[h], Hacc[h]);
        }
    }

    float l0 = sfcb[0], l1 = sfcb[1];
#pragma unroll
    for (int h = 0; h < 16; h++) {
        l0 = fmaf(Hacc[h], sfcW[h * 2 + 0], l0);
        l1 = fmaf(Hacc[h], sfcW[h * 2 + 1], l1);
    }
    float m = fmaxf(l0, l1);
    float lse = m + logf(expf(l0 - m) + expf(l1 - m));
    out[(size_t)node * 2 + 0] = l0 - lse;
    out[(size_t)node * 2 + 1] = l1 - lse;
}

// ---------------- launch ----------------
extern "C" void kernel_launch(void* const* d_in, const int* in_sizes, int n_in,
                              void* d_out, int out_size) {
    const float* x   = (const float*)d_in[0];
    const int*   src = (const int*)d_in[1];
    const int*   dst = (const int*)d_in[2];
    const float* W1  = (const float*)d_in[3];
    const float* b1  = (const float*)d_in[4];
    const float* W2  = (const float*)d_in[5];
    const float* b2  = (const float*)d_in[6];
    const float* Wz  = (const float*)d_in[7];
    const float* bz  = (const float*)d_in[8];
    const float* Wr  = (const float*)d_in[9];
    const float* br  = (const float*)d_in[10];
    const float* Wh  = (const float*)d_in[11];
    const float* bh  = (const float*)d_in[12];
    const float* Lz  = (const float*)d_in[13];
    const float* lz  = (const float*)d_in[14];
    const float* Lr  = (const float*)d_in[15];
    const float* lr  = (const float*)d_in[16];
    const float* Lh  = (const float*)d_in[17];
    const float* lh  = (const float*)d_in[18];
    const float* att = (const float*)d_in[19];
    const float* fcW = (const float*)d_in[20];
    const float* fcb = (const float*)d_in[21];

    int n = in_sizes[0] / (TT * FIN);
    int e = in_sizes[1];

    void* p;
    cudaGetSymbolAddress(&p, g_cursor);  int*           cursor = (int*)p;
    cudaGetSymbolAddress(&p, g_dis);     float*         dis    = (float*)p;
    cudaGetSymbolAddress(&p, g_csrc);    int*           csrc   = (int*)p;
    cudaGetSymbolAddress(&p, g_xT);      __half*        xT     = (__half*)p;
    cudaGetSymbolAddress(&p, g_h1);      unsigned char* h1     = (unsigned char*)p;
    cudaGetSymbolAddress(&p, g_feats);   unsigned char* feats  = (unsigned char*)p;
    cudaGetSymbolAddress(&p, g_P);       __half*        P      = (__half*)p;

    int nb256_n = (n + 255) / 256;
    int e8 = (e + 7) / 8;
    int prop_blocks = (n + 7) / 8;

    // 0: fold GRU gate weights
    kprepG<<<1, 256>>>(Wz, bz, Wr, br, Wh, bh, Lz, lz, Lr, lr, Lh, lh);
    // 1: cursor init (fixed-capacity slices)
    kinit<<<nb256_n, 256>>>(cursor, n);
    // 2: single-pass edge fill
    kfill<<<(e8 + 255) / 256, 256>>>(src, dst, cursor, csrc, e);
    // 3: x transpose pre-scaled by dis (from cursor)
    ktransd<<<(n * XREAL2 + 255) / 256, 256>>>(x, xT, cursor, dis, n);
    // 4: h1(fp8) = K8*dis*relu((S x) @ W1 + b1)   [dual-row gather]
    kprop_x<<<prop_blocks, 256>>>(xT, h1, cursor, csrc, dis, W1, b1, n);
    // 5: feats(fp8) = K8*dis*relu((S h1) @ W2 + b2)
    kprop8<1><<<prop_blocks, 256>>>(h1, feats, cursor, csrc, dis, W2, b2, n);
    // 6: P(fp16) = S feats
    kprop8<0><<<prop_blocks, 256>>>(feats, P, cursor, csrc, dis, W2, b2, n);
    // 7: GRU (FFMA2) + attention + FC + log_softmax
    kgru<<<(n + GRU_NPB - 1) / GRU_NPB, GRU_NPB>>>(P, Lz, Lr, Lh, att, fcW, fcb,
                                                   (float*)d_out, n);
}

// round 15
// speedup vs baseline: 1.0710x; 1.0201x over previous
#include <cuda_runtime.h>
#include <cuda_fp16.h>
#include <math.h>
#include <stdint.h>

// Problem constants (fixed by the dataset)
#define TT 5
#define FIN 10
#define HID 16
#define MAXN 100000
#define MAXE 3200000
#define CAP 96            // fixed CSR slice capacity per node (divisible by 3 and 4)
#define XSTRIDE 64        // xT row stride in halves -> 128B aligned rows
#define XREAL  50
#define XREAL2 25         // half2 elements per xT row
#define F8STRIDE 128      // fp8 feature row stride in BYTES (80 data + pad)
#define FSTRIDE 80        // P row stride in halves (fp16)
#define K8 16.0f          // fp8 storage scale

// ---------------- device scratch (static: no allocation allowed) ----------------
// Feature arrays sized MAXN+1: row MAXN (well, row index n) is the all-zero dummy
// row used by the triple-gather padding. It is never written, so the .bss zero
// persists across graph replays.
__device__ int    g_cursor[MAXN];
__device__ float  g_dis[MAXN];
__device__ __align__(16) int           g_csrc[(size_t)MAXN * CAP];
__device__ __align__(16) __half        g_xT[(size_t)(MAXN + 1) * XSTRIDE];
__device__ __align__(16) unsigned char g_h1[(size_t)(MAXN + 1) * F8STRIDE];
__device__ __align__(16) unsigned char g_feats[(size_t)(MAXN + 1) * F8STRIDE];
__device__ __align__(16) __half        g_P[(size_t)(MAXN + 1) * FSTRIDE];
__device__ float  g_Mz[256], g_Mr[256], g_Mh[256];
__device__ float  g_Bz[16],  g_Br[16],  g_Bh[16];

__device__ __forceinline__ __half2 bits_h2u(unsigned b) {
    return *reinterpret_cast<__half2*>(&b);
}
__device__ __forceinline__ float fast_tanh(float x) {
    float r;
    asm("tanh.approx.f32 %0, %1;" : "=f"(r) : "f"(x));
    return r;
}
__device__ __forceinline__ float fast_sig(float x) {
    return fmaf(0.5f, fast_tanh(0.5f * x), 0.5f);
}
// packed fp32x2 helpers (Blackwell FFMA2 — PTX-only)
__device__ __forceinline__ unsigned long long pack2(float lo, float hi) {
    unsigned long long r;
    asm("mov.b64 %0, {%1, %2};" : "=l"(r) : "f"(lo), "f"(hi));
    return r;
}
__device__ __forceinline__ void unpack2(float& lo, float& hi, unsigned long long v) {
    asm("mov.b64 {%0, %1}, %2;" : "=f"(lo), "=f"(hi) : "l"(v));
}
__device__ __forceinline__ unsigned long long fma2(unsigned long long a,
                                                   unsigned long long b,
                                                   unsigned long long c) {
    unsigned long long d;
    asm("fma.rn.f32x2 %0, %1, %2, %3;" : "=l"(d) : "l"(a), "l"(b), "l"(c));
    return d;
}
// fp8 e4m3 pack/unpack
__device__ __forceinline__ unsigned pack_e4m3x4(float a, float b, float c, float d) {
    unsigned short lo, hi;
    asm("cvt.rn.satfinite.e4m3x2.f32 %0, %1, %2;" : "=h"(lo) : "f"(b), "f"(a));
    asm("cvt.rn.satfinite.e4m3x2.f32 %0, %1, %2;" : "=h"(hi) : "f"(d), "f"(c));
    return (unsigned)lo | ((unsigned)hi << 16);
}
__device__ __forceinline__ void unpack_e4m3x4(unsigned q, __half2& p01, __half2& p23) {
    unsigned a, b;
    asm("{\n\t"
        ".reg .b16 lo, hi;\n\t"
        "mov.b32 {lo, hi}, %2;\n\t"
        "cvt.rn.f16x2.e4m3x2 %0, lo;\n\t"
        "cvt.rn.f16x2.e4m3x2 %1, hi;\n\t"
        "}" : "=r"(a), "=r"(b) : "r"(q));
    p01 = bits_h2u(a);
    p23 = bits_h2u(b);
}

// ---------------- stage 1: cursor init -------------------------------------------
__global__ void kinit(int* cursor, int n) {
    int i = blockIdx.x * blockDim.x + threadIdx.x;
    if (i < n) cursor[i] = i * CAP;
}

// ---------------- stage 2: edge fill into fixed slices (single atomic pass) ------
__global__ void kfill(const int* __restrict__ src, const int* __restrict__ dst,
                      int* cursor, int* csrc, int e) {
    int i = blockIdx.x * blockDim.x + threadIdx.x;
    int j = i * 8;
    if (j + 8 <= e) {
        int4 s0 = __ldg((const int4*)(src + j));
        int4 s1 = __ldg((const int4*)(src + j + 4));
        int4 d0 = __ldg((const int4*)(dst + j));
        int4 d1 = __ldg((const int4*)(dst + j + 4));
        int p;
        p = atomicAdd(&cursor[d0.x], 1); if (p < d0.x * CAP + CAP) csrc[p] = s0.x;
        p = atomicAdd(&cursor[d0.y], 1); if (p < d0.y * CAP + CAP) csrc[p] = s0.y;
        p = atomicAdd(&cursor[d0.z], 1); if (p < d0.z * CAP + CAP) csrc[p] = s0.z;
        p = atomicAdd(&cursor[d0.w], 1); if (p < d0.w * CAP + CAP) csrc[p] = s0.w;
        p = atomicAdd(&cursor[d1.x], 1); if (p < d1.x * CAP + CAP) csrc[p] = s1.x;
        p = atomicAdd(&cursor[d1.y], 1); if (p < d1.y * CAP + CAP) csrc[p] = s1.y;
        p = atomicAdd(&cursor[d1.z], 1); if (p < d1.z * CAP + CAP) csrc[p] = s1.z;
        p = atomicAdd(&cursor[d1.w], 1); if (p < d1.w * CAP + CAP) csrc[p] = s1.w;
    } else {
        for (; j < e; j++) {
            int d = __ldg(dst + j);
            int p = atomicAdd(&cursor[d], 1);
            if (p < d * CAP + CAP) csrc[p] = __ldg(src + j);
        }
    }
}

// ---------------- stage 3: x transpose (pre-scaled) + dis + slice pad-to-3 ------
__global__ void ktransd(const float* __restrict__ x, __half* __restrict__ xT,
                        const int* __restrict__ cursor, float* __restrict__ dis,
                        int* __restrict__ csrc, int n) {
    int i = blockIdx.x * blockDim.x + threadIdx.x;
    if (i >= n * XREAL2) return;
    int node = i / XREAL2;
    int c2 = i - node * XREAL2;
    int base = node * CAP;
    int endc = __ldg(cursor + node);
    if (endc > base + CAP) endc = base + CAP;
    int deg = endc - base;
    float dd = rsqrtf((float)deg + 1.0f);
    if (c2 == 0) {
        dis[node] = dd;
        int r = deg % 3;                       // pad slice to multiple of 3 with
        if (r) {                               // the dummy (all-zero) row index n
            csrc[endc] = n;
            if (r == 1) csrc[endc + 1] = n;
        }
    }
    int c = 2 * c2;
    int t = c / FIN;
    int f = c - t * FIN;
    float2 v = __ldg((const float2*)(x + ((size_t)t * n + node) * FIN + f));
    __half2 h = __floats2half2_rn(dd * v.x, dd * v.y);
    ((unsigned*)xT)[(size_t)node * (XSTRIDE / 2) + c2] =
        *reinterpret_cast<unsigned*>(&h);
}

// ---------------- stage 4: dual-row fp16 gather-sum -> fp8 transformed output ----
__global__ __launch_bounds__(256, 8) void kprop_x(const __half* __restrict__ in,
                                                  unsigned char* __restrict__ out,
                                                  const int* __restrict__ cursor,
                                                  const int* __restrict__ csrc,
                                                  const float* __restrict__ dis,
                                                  const float* __restrict__ Wm,
                                                  const float* __restrict__ bm, int n) {
    __shared__ float sAgg[8][52];
    __shared__ float sW[FIN * 16];
    __shared__ float sB[16];
    for (int i = threadIdx.x; i < FIN * 16; i += blockDim.x) sW[i] = Wm[i];
    if (threadIdx.x < 16) sB[threadIdx.x] = bm[threadIdx.x];
    __syncthreads();

    int wwid = threadIdx.x >> 5;
    int node = (blockIdx.x << 3) + wwid;
    if (node >= n) return;
    int lane = threadIdx.x & 31;
    bool grp = lane >= 16;
    int lh = lane & 15;
    int ll = (lh < 13) ? lh : 12;
    const unsigned FULL = 0xffffffffu;

    __half2 zero2 = __float2half2_rn(0.f);
    __half2 a0x = zero2, a0y = zero2, a1x = zero2, a1y = zero2;

    int j = node * CAP;
    int end = __ldg(cursor + node);
    if (end > j + CAP) end = j + CAP;

    for (; j + 4 <= end; j += 4) {
        int4 e4 = __ldg((const int4*)(csrc + j));
        int sA = grp ? e4.y : e4.x;
        int sB2 = grp ? e4.w : e4.z;
        uint2 q0 = __ldg((const uint2*)(in + (size_t)sA * XSTRIDE) + ll);
        uint2 q1 = __ldg((const uint2*)(in + (size_t)sB2 * XSTRIDE) + ll);
        a0x = __hadd2(a0x, bits_h2u(q0.x));
        a0y = __hadd2(a0y, bits_h2u(q0.y));
        a1x = __hadd2(a1x, bits_h2u(q1.x));
        a1y = __hadd2(a1y, bits_h2u(q1.y));
    }
    if (j + 2 <= end) {
        int sA = csrc[j + (grp ? 1 : 0)];
        uint2 q = __ldg((const uint2*)(in + (size_t)sA * XSTRIDE) + ll);
        a0x = __hadd2(a0x, bits_h2u(q.x));
        a0y = __hadd2(a0y, bits_h2u(q.y));
        j += 2;
    }
    if (j < end) {
        int s = csrc[j];
        uint2 q = __ldg((const uint2*)(in + (size_t)s * XSTRIDE) + ll);
        if (!grp) {
            a0x = __hadd2(a0x, bits_h2u(q.x));
            a0y = __hadd2(a0y, bits_h2u(q.y));
        }
    }

    float2 c0 = __half22float2(a0x);
    float2 c1 = __half22float2(a1x);
    float f0 = c0.x + c1.x;
    float f1 = c0.y + c1.y;
    c0 = __half22float2(a0y);
    c1 = __half22float2(a1y);
    float f2 = c0.x + c1.x;
    float f3 = c0.y + c1.y;
    f0 += __shfl_down_sync(FULL, f0, 16);
    f1 += __shfl_down_sync(FULL, f1, 16);
    f2 += __shfl_down_sync(FULL, f2, 16);
    f3 += __shfl_down_sync(FULL, f3, 16);

    float dd = __ldg(dis + node);
    uint2 sq = __ldg((const uint2*)(in + (size_t)node * XSTRIDE) + ll);
    float2 s01 = __half22float2(bits_h2u(sq.x));
    float2 s23 = __half22float2(bits_h2u(sq.y));
    f0 = dd * (f0 + s01.x);
    f1 = dd * (f1 + s01.y);
    f2 = dd * (f2 + s23.x);
    f3 = dd * (f3 + s23.y);

    if (lane < 13) {
        float4 fv = make_float4(f0, f1, f2, f3);
        *(float4*)&sAgg[wwid][lane * 4] = fv;
    }
    __syncwarp();
    if (lane < 20) {
        float ks = K8 * dd;
        int c = lane * 4;
        int t = c >> 4;
        int h = c & 15;
        float o0 = sB[h], o1 = sB[h + 1], o2 = sB[h + 2], o3 = sB[h + 3];
#pragma unroll
        for (int f = 0; f < FIN; f++) {
            float a = sAgg[wwid][t * FIN + f];
            o0 = fmaf(a, sW[f * 16 + h],     o0);
            o1 = fmaf(a, sW[f * 16 + h + 1], o1);
            o2 = fmaf(a, sW[f * 16 + h + 2], o2);
            o3 = fmaf(a, sW[f * 16 + h + 3], o3);
        }
        unsigned pk = pack_e4m3x4(ks * fmaxf(o0, 0.f), ks * fmaxf(o1, 0.f),
                                  ks * fmaxf(o2, 0.f), ks * fmaxf(o3, 0.f));
        ((unsigned*)(out + (size_t)node * F8STRIDE))[lane] = pk;
    }
}

// ---------------- stages 5/6: TRIPLE-row fp8 gather-sum ---------------------------
// Lanes 0-9 / 10-19 / 20-29 each gather one edge's 80B row as 10 uint2s: one LDG
// serves 3 edges; the cvt/hadd2 stream also covers 3 edges per instruction.
// Slices are padded to a multiple of 3 with the zero dummy row (index n).
template <int MODE>
__global__ __launch_bounds__(256, 8) void kprop8(const unsigned char* __restrict__ in,
                                                 void* __restrict__ outv,
                                                 const int* __restrict__ cursor,
                                                 const int* __restrict__ csrc,
                                                 const float* __restrict__ dis,
                                                 const float* __restrict__ Wm,
                                                 const float* __restrict__ bm, int n) {
    __shared__ float sAgg[MODE ? 8 : 1][MODE ? 80 : 4];
    __shared__ float sW[MODE ? HID * 16 : 1];
    __shared__ float sB[MODE ? 16 : 1];
    if (MODE) {
        for (int i = threadIdx.x; i < HID * 16; i += blockDim.x) sW[i] = Wm[i];
        if (threadIdx.x < 16) sB[threadIdx.x] = bm[threadIdx.x];
        __syncthreads();
    }
    int wwid = threadIdx.x >> 5;
    int node = (blockIdx.x << 3) + wwid;
    if (node >= n) return;
    int lane = threadIdx.x & 31;
    int g = lane / 10; if (g > 2) g = 2;       // lanes 30,31 duplicate group 2
    int lh = lane - g * 10; if (lh > 9) lh = 9;
    const unsigned FULL = 0xffffffffu;

    __half2 zero2 = __float2half2_rn(0.f);
    __half2 a0 = zero2, a1 = zero2, a2 = zero2, a3 = zero2;

    int base = node * CAP;
    int end = __ldg(cursor + node);
    if (end > base + CAP) end = base + CAP;
    int end3 = base + ((end - base + 2) / 3) * 3;   // padded region is valid

    int j = base;
    for (; j + 6 <= end3; j += 6) {
        int s0 = __ldg(csrc + j + g);
        int s1 = __ldg(csrc + j + 3 + g);
        uint2 q0 = __ldg((const uint2*)(in + (size_t)s0 * F8STRIDE) + lh);
        uint2 q1 = __ldg((const uint2*)(in + (size_t)s1 * F8STRIDE) + lh);
        __half2 pa, pb;
        unpack_e4m3x4(q0.x, pa, pb); a0 = __hadd2(a0, pa); a1 = __hadd2(a1, pb);
        unpack_e4m3x4(q0.y, pa, pb); a2 = __hadd2(a2, pa); a3 = __hadd2(a3, pb);
        unpack_e4m3x4(q1.x, pa, pb); a0 = __hadd2(a0, pa); a1 = __hadd2(a1, pb);
        unpack_e4m3x4(q1.y, pa, pb); a2 = __hadd2(a2, pa); a3 = __hadd2(a3, pb);
    }
    if (j < end3) {
        int s0 = __ldg(csrc + j + g);
        uint2 q0 = __ldg((const uint2*)(in + (size_t)s0 * F8STRIDE) + lh);
        __half2 pa, pb;
        unpack_e4m3x4(q0.x, pa, pb); a0 = __hadd2(a0, pa); a1 = __hadd2(a1, pb);
        unpack_e4m3x4(q0.y, pa, pb); a2 = __hadd2(a2, pa); a3 = __hadd2(a3, pb);
    }

    // per-lane partials (cols lh*8 .. lh*8+7) in fp32
    float v[8];
    float2 t2;
    t2 = __half22float2(a0); v[0] = t2.x; v[1] = t2.y;
    t2 = __half22float2(a1); v[2] = t2.x; v[3] = t2.y;
    t2 = __half22float2(a2); v[4] = t2.x; v[5] = t2.y;
    t2 = __half22float2(a3); v[6] = t2.x; v[7] = t2.y;
    // cross-group merge: group-0 lane lh pulls group1 (lh+10) and group2 (lh+20)
#pragma unroll
    for (int k = 0; k < 8; k++) {
        float b1v = __shfl_sync(FULL, v[k], lh + 10);
        float b2v = __shfl_sync(FULL, v[k], lh + 20);
        v[k] += b1v + b2v;
    }

    float dd = __ldg(dis + node);
    float sc = dd * (1.0f / K8);
    uint2 sq = __ldg((const uint2*)(in + (size_t)node * F8STRIDE) + lh);
    __half2 sa, sb;
    unpack_e4m3x4(sq.x, sa, sb);
    float2 s01 = __half22float2(sa), s23 = __half22float2(sb);
    v[0] = sc * (v[0] + s01.x); v[1] = sc * (v[1] + s01.y);
    v[2] = sc * (v[2] + s23.x); v[3] = sc * (v[3] + s23.y);
    unpack_e4m3x4(sq.y, sa, sb);
    s01 = __half22float2(sa); s23 = __half22float2(sb);
    v[4] = sc * (v[4] + s01.x); v[5] = sc * (v[5] + s01.y);
    v[6] = sc * (v[6] + s23.x); v[7] = sc * (v[7] + s23.y);

    if (!MODE) {
        if (lane < 10) {
            __half2 p0 = __floats2half2_rn(v[0], v[1]);
            __half2 p1 = __floats2half2_rn(v[2], v[3]);
            __half2 p2 = __floats2half2_rn(v[4], v[5]);
            __half2 p3 = __floats2half2_rn(v[6], v[7]);
            uint4 pk;
            pk.x = *reinterpret_cast<unsigned*>(&p0);
            pk.y = *reinterpret_cast<unsigned*>(&p1);
            pk.z = *reinterpret_cast<unsigned*>(&p2);
            pk.w = *reinterpret_cast<unsigned*>(&p3);
            *((uint4*)((__half*)outv + (size_t)node * FSTRIDE) + lh) = pk;
        }
        return;
    }

    if (lane < 10) {
        *(float4*)&sAgg[wwid][lh * 8]     = make_float4(v[0], v[1], v[2], v[3]);
        *(float4*)&sAgg[wwid][lh * 8 + 4] = make_float4(v[4], v[5], v[6], v[7]);
    }
    __syncwarp();
    if (lane < 20) {
        float ks = K8 * dd;
        int c = lane * 4;
        int t = c >> 4;
        int h = c & 15;
        float o0 = sB[h], o1 = sB[h + 1], o2 = sB[h + 2], o3 = sB[h + 3];
#pragma unroll
        for (int f = 0; f < HID; f++) {
            float a = sAgg[wwid][t * HID + f];
            o0 = fmaf(a, sW[f * 16 + h],     o0);
            o1 = fmaf(a, sW[f * 16 + h + 1], o1);
            o2 = fmaf(a, sW[f * 16 + h + 2], o2);
            o3 = fmaf(a, sW[f * 16 + h + 3], o3);
        }
        unsigned pk = pack_e4m3x4(ks * fmaxf(o0, 0.f), ks * fmaxf(o1, 0.f),
                                  ks * fmaxf(o2, 0.f), ks * fmaxf(o3, 0.f));
        ((unsigned*)((unsigned char*)outv + (size_t)node * F8STRIDE))[lane] = pk;
    }
}

// ---------------- fold gate matmuls ----------------------------------------------
__global__ void kprepG(const float* Wz, const float* bz, const float* Wr, const float* br,
                       const float* Wh, const float* bh,
                       const float* Lz, const float* lz, const float* Lr, const float* lr,
                       const float* Lh, const float* lh) {
    int tid = threadIdx.x;  // 256
    int k = tid >> 4, h = tid & 15;
    float mz = 0.f, mr = 0.f, mh = 0.f;
#pragma unroll
    for (int j = 0; j < 16; j++) {
        mz = fmaf(Wz[k * 16 + j], Lz[j * 16 + h], mz);
        mr = fmaf(Wr[k * 16 + j], Lr[j * 16 + h], mr);
        mh = fmaf(Wh[k * 16 + j], Lh[j * 16 + h], mh);
    }
    g_Mz[tid] = mz; g_Mr[tid] = mr; g_Mh[tid] = mh;
    if (tid < 16) {
        float az = lz[tid], ar = lr[tid], ah = lh[tid];
#pragma unroll
        for (int j = 0; j < 16; j++) {
            az = fmaf(bz[j], Lz[j * 16 + tid], az);
            ar = fmaf(br[j], Lr[j * 16 + tid], ar);
            ah = fmaf(bh[j], Lh[j * 16 + tid], ah);
        }
        g_Bz[tid] = az; g_Br[tid] = ar; g_Bh[tid] = ah;
    }
}

// ---------------- GRU (FFMA2, half2-staged P) + attention + FC + log_softmax ----
#define GRU_NPB 96
__global__ __launch_bounds__(GRU_NPB) void kgru(const __half* __restrict__ P,
                                                const float* __restrict__ Lz,
                                                const float* __restrict__ Lr,
                                                const float* __restrict__ Lh,
                                                const float* __restrict__ att,
                                                const float* __restrict__ fcW,
                                                const float* __restrict__ fcb,
                                                float* __restrict__ out, int n) {
    __shared__ unsigned long long sM2z[128], sM2r[128], sM2h[128];
    __shared__ unsigned long long sL2z[128], sL2r[128], sL2h[128];
    __shared__ unsigned long long sB2z[8], sB2r[8], sB2h[8];
    __shared__ unsigned sPh[GRU_NPB * 41];
    __shared__ float sfcW[32], sfcb[2], sprob[TT];

    int tid = threadIdx.x;
    for (int i = tid; i < 128; i += GRU_NPB) {
        int k = i >> 3, j = i & 7;
        int gi = k * 16 + 2 * j;
        sM2z[i] = pack2(g_Mz[gi], g_Mz[gi + 1]);
        sM2r[i] = pack2(g_Mr[gi], g_Mr[gi + 1]);
        sM2h[i] = pack2(g_Mh[gi], g_Mh[gi + 1]);
        sL2z[i] = pack2(Lz[256 + gi], Lz[256 + gi + 1]);
        sL2r[i] = pack2(Lr[256 + gi], Lr[256 + gi + 1]);
        sL2h[i] = pack2(Lh[256 + gi], Lh[256 + gi + 1]);
    }
    if (tid < 8) {
        sB2z[tid] = pack2(g_Bz[2 * tid], g_Bz[2 * tid + 1]);
        sB2r[tid] = pack2(g_Br[2 * tid], g_Br[2 * tid + 1]);
        sB2h[tid] = pack2(g_Bh[2 * tid], g_Bh[2 * tid + 1]);
    }
    if (tid < 32) sfcW[tid] = fcW[tid];
    if (tid < 2)  sfcb[tid] = fcb[tid];
    if (tid == 0) {
        float m = att[0];
        for (int t = 1; t < TT; t++) m = fmaxf(m, att[t]);
        float ex[TT]; float s = 0.f;
        for (int t = 0; t < TT; t++) { ex[t] = expf(att[t] - m); s += ex[t]; }
        for (int t = 0; t < TT; t++) sprob[t] = ex[t] / s;
    }
    int base = blockIdx.x * GRU_NPB;
    for (int i = tid; i < GRU_NPB * (FSTRIDE / 2); i += GRU_NPB) {
        int nd = i / (FSTRIDE / 2), c2 = i - nd * (FSTRIDE / 2);
        int g = base + nd;
        unsigned u = 0;
        if (g < n) u = __ldg((const unsigned*)(P + (size_t)g * FSTRIDE) + c2);
        sPh[nd * 41 + c2] = u;
    }
    __syncthreads();

    int node = base + tid;
    if (node >= n) return;
    const unsigned* myPh = &sPh[tid * 41];

    float H[16], Hacc[16];
#pragma unroll
    for (int h = 0; h < 16; h++) { H[h] = 0.f; Hacc[h] = 0.f; }

#pragma unroll 1
    for (int t = 0; t < TT; t++) {
        unsigned long long pk2[16], hk2[16];
#pragma unroll
        for (int k2 = 0; k2 < 8; k2++) {
            float2 pf = __half22float2(bits_h2u(myPh[t * 8 + k2]));
            pk2[2 * k2]     = pack2(pf.x, pf.x);
            pk2[2 * k2 + 1] = pack2(pf.y, pf.y);
        }
#pragma unroll
        for (int k = 0; k < 16; k++) hk2[k] = pack2(H[k], H[k]);

        unsigned long long acc[8];
        float a[16];
#pragma unroll
        for (int j = 0; j < 8; j++) acc[j] = sB2z[j];
#pragma unroll
        for (int k = 0; k < 16; k++) {
#pragma unroll
            for (int j = 0; j < 8; j++) {
                acc[j] = fma2(pk2[k], sM2z[k * 8 + j], acc[j]);
                acc[j] = fma2(hk2[k], sL2z[k * 8 + j], acc[j]);
            }
        }
        float Zg[16];
#pragma unroll
        for (int j = 0; j < 8; j++) unpack2(a[2 * j], a[2 * j + 1], acc[j]);
#pragma unroll
        for (int h = 0; h < 16; h++) Zg[h] = fast_sig(a[h]);

#pragma unroll
        for (int j = 0; j < 8; j++) acc[j] = sB2r[j];
#pragma unroll
        for (int k = 0; k < 16; k++) {
#pragma unroll
            for (int j = 0; j < 8; j++) {
                acc[j] = fma2(pk2[k], sM2r[k * 8 + j], acc[j]);
                acc[j] = fma2(hk2[k], sL2r[k * 8 + j], acc[j]);
            }
        }
        float Rg[16];
#pragma unroll
        for (int j = 0; j < 8; j++) unpack2(a[2 * j], a[2 * j + 1], acc[j]);
#pragma unroll
        for (int h = 0; h < 16; h++) Rg[h] = fast_sig(a[h]);

#pragma unroll
        for (int k = 0; k < 16; k++) {
            float hr = H[k] * Rg[k];
            hk2[k] = pack2(hr, hr);
        }
#pragma unroll
        for (int j = 0; j < 8; j++) acc[j] = sB2h[j];
#pragma unroll
        for (int k = 0; k < 16; k++) {
#pragma unroll
            for (int j = 0; j < 8; j++) {
                acc[j] = fma2(pk2[k], sM2h[k * 8 + j], acc[j]);
                acc[j] = fma2(hk2[k], sL2h[k * 8 + j], acc[j]);
            }
        }
#pragma unroll
        for (int j = 0; j < 8; j++) unpack2(a[2 * j], a[2 * j + 1], acc[j]);
#pragma unroll
        for (int h = 0; h < 16; h++) {
            float ht = fast_tanh(a[h]);
            H[h] = Zg[h] * H[h] + (1.f - Zg[h]) * ht;
            Hacc[h] = fmaf(sprob[t], H[h], Hacc[h]);
        }
    }

    float l0 = sfcb[0], l1 = sfcb[1];
#pragma unroll
    for (int h = 0; h < 16; h++) {
        l0 = fmaf(Hacc[h], sfcW[h * 2 + 0], l0);
        l1 = fmaf(Hacc[h], sfcW[h * 2 + 1], l1);
    }
    float m = fmaxf(l0, l1);
    float lse = m + logf(expf(l0 - m) + expf(l1 - m));
    out[(size_t)node * 2 + 0] = l0 - lse;
    out[(size_t)node * 2 + 1] = l1 - lse;
}

// ---------------- launch ----------------
extern "C" void kernel_launch(void* const* d_in, const int* in_sizes, int n_in,
                              void* d_out, int out_size) {
    const float* x   = (const float*)d_in[0];
    const int*   src = (const int*)d_in[1];
    const int*   dst = (const int*)d_in[2];
    const float* W1  = (const float*)d_in[3];
    const float* b1  = (const float*)d_in[4];
    const float* W2  = (const float*)d_in[5];
    const float* b2  = (const float*)d_in[6];
    const float* Wz  = (const float*)d_in[7];
    const float* bz  = (const float*)d_in[8];
    const float* Wr  = (const float*)d_in[9];
    const float* br  = (const float*)d_in[10];
    const float* Wh  = (const float*)d_in[11];
    const float* bh  = (const float*)d_in[12];
    const float* Lz  = (const float*)d_in[13];
    const float* lz  = (const float*)d_in[14];
    const float* Lr  = (const float*)d_in[15];
    const float* lr  = (const float*)d_in[16];
    const float* Lh  = (const float*)d_in[17];
    const float* lh  = (const float*)d_in[18];
    const float* att = (const float*)d_in[19];
    const float* fcW = (const float*)d_in[20];
    const float* fcb = (const float*)d_in[21];

    int n = in_sizes[0] / (TT * FIN);
    int e = in_sizes[1];

    void* p;
    cudaGetSymbolAddress(&p, g_cursor);  int*           cursor = (int*)p;
    cudaGetSymbolAddress(&p, g_dis);     float*         dis    = (float*)p;
    cudaGetSymbolAddress(&p, g_csrc);    int*           csrc   = (int*)p;
    cudaGetSymbolAddress(&p, g_xT);      __half*        xT     = (__half*)p;
    cudaGetSymbolAddress(&p, g_h1);      unsigned char* h1     = (unsigned char*)p;
    cudaGetSymbolAddress(&p, g_feats);   unsigned char* feats  = (unsigned char*)p;
    cudaGetSymbolAddress(&p, g_P);       __half*        P      = (__half*)p;

    int nb256_n = (n + 255) / 256;
    int e8 = (e + 7) / 8;
    int prop_blocks = (n + 7) / 8;

    // 0: fold GRU gate weights
    kprepG<<<1, 256>>>(Wz, bz, Wr, br, Wh, bh, Lz, lz, Lr, lr, Lh, lh);
    // 1: cursor init (fixed-capacity slices)
    kinit<<<nb256_n, 256>>>(cursor, n);
    // 2: single-pass edge fill
    kfill<<<(e8 + 255) / 256, 256>>>(src, dst, cursor, csrc, e);
    // 3: x transpose (pre-scaled) + dis + slice pad-to-3
    ktransd<<<(n * XREAL2 + 255) / 256, 256>>>(x, xT, cursor, dis, csrc, n);
    // 4: h1(fp8) = K8*dis*relu((S x) @ W1 + b1)   [dual-row gather]
    kprop_x<<<prop_blocks, 256>>>(xT, h1, cursor, csrc, dis, W1, b1, n);
    // 5: feats(fp8) = K8*dis*relu((S h1) @ W2 + b2)   [triple-row gather]
    kprop8<1><<<prop_blocks, 256>>>(h1, feats, cursor, csrc, dis, W2, b2, n);
    // 6: P(fp16) = S feats                            [triple-row gather]
    kprop8<0><<<prop_blocks, 256>>>(feats, P, cursor, csrc, dis, W2, b2, n);
    // 7: GRU (FFMA2) + attention + FC + log_softmax
    kgru<<<(n + GRU_NPB - 1) / GRU_NPB, GRU_NPB>>>(P, Lz, Lr, Lh, att, fcW, fcb,
                                                   (float*)d_out, n);
}